// round 8
// baseline (speedup 1.0000x reference)
#include <cuda_runtime.h>
#include <cuda_bf16.h>
#include <math.h>
#include <stdint.h>

// ---------------------------------------------------------------------------
// Problem constants
// ---------------------------------------------------------------------------
#define BSZ   4
#define LEN   2048
#define DIM   1024
#define NH    8
#define NE    16
#define TOPK  2
#define HD    128
#define II    512
#define NTOK  (BSZ*LEN)    // 8192
#define NSUB  (NTOK*NH)    // 65536
#define NPAIR (NSUB*TOPK)  // 131072

// ---------------------------------------------------------------------------
// Device scratch (activations packed as bf16x2 hi/lo along k)
// ---------------------------------------------------------------------------
__device__ uint32_t g_xH [(size_t)NTOK * DIM / 2];
__device__ uint32_t g_xL [(size_t)NTOK * DIM / 2];
__device__ uint32_t g_hH [(size_t)NTOK * DIM / 2];
__device__ uint32_t g_hL [(size_t)NTOK * DIM / 2];
__device__ uint32_t g_mH [(size_t)NPAIR * II / 2];
__device__ uint32_t g_mL [(size_t)NPAIR * II / 2];
__device__ float    g_eo [(size_t)NPAIR * HD];
__device__ uint32_t g_cH [(size_t)NTOK * DIM / 2];
__device__ uint32_t g_cL [(size_t)NTOK * DIM / 2];
__device__ int   g_topi[NPAIR];
__device__ float g_topw[NPAIR];
__device__ int   g_perm[NPAIR];
__device__ int   g_pos [NPAIR];
__device__ int   g_counts[NE];
__device__ int   g_cursor[NE];
__device__ int   g_offsets[NE + 1];

// Prepacked weights: hi/lo bf16x2 (packed along k), transposed to [N][K/2]
__device__ uint32_t g_WmH[(size_t)DIM * DIM / 2];
__device__ uint32_t g_WmL[(size_t)DIM * DIM / 2];
__device__ uint32_t g_W1H[(size_t)NE * II * HD / 2];
__device__ uint32_t g_W1L[(size_t)NE * II * HD / 2];
__device__ uint32_t g_W2H[(size_t)NE * HD * II / 2];
__device__ uint32_t g_W2L[(size_t)NE * HD * II / 2];
__device__ uint32_t g_WoH[(size_t)DIM * DIM / 2];
__device__ uint32_t g_WoL[(size_t)DIM * DIM / 2];

// ---------------------------------------------------------------------------
// Helpers
// ---------------------------------------------------------------------------
__device__ __forceinline__ float gelu_exact(float x) {
    return 0.5f * x * (1.0f + erff(x * 0.70710678118654752440f));
}
__device__ __forceinline__ uint32_t pack_bf16x2(float e0, float e1) {
    uint32_t r;
    asm("cvt.rn.bf16x2.f32 %0, %1, %2;" : "=r"(r) : "f"(e1), "f"(e0));
    return r;
}
__device__ __forceinline__ float bf16_rt(float x) {
    return __bfloat162float(__float2bfloat16(x));
}
__device__ __forceinline__ float2 unpack_bf16x2(uint32_t v) {
    __nv_bfloat162 b = *reinterpret_cast<__nv_bfloat162*>(&v);
    return __bfloat1622float2(b);
}
__device__ __forceinline__ void mma_bf16(float* d, const uint32_t* a, const uint32_t* b) {
    asm volatile(
        "mma.sync.aligned.m16n8k16.row.col.f32.bf16.bf16.f32 "
        "{%0,%1,%2,%3}, {%4,%5,%6,%7}, {%8,%9}, {%0,%1,%2,%3};\n"
        : "+f"(d[0]), "+f"(d[1]), "+f"(d[2]), "+f"(d[3])
        : "r"(a[0]), "r"(a[1]), "r"(a[2]), "r"(a[3]), "r"(b[0]), "r"(b[1]));
}
__device__ __forceinline__ void ldsm_x4(uint32_t& r0, uint32_t& r1,
                                        uint32_t& r2, uint32_t& r3, uint32_t addr) {
    asm volatile("ldmatrix.sync.aligned.m8n8.x4.shared.b16 {%0,%1,%2,%3}, [%4];"
                 : "=r"(r0), "=r"(r1), "=r"(r2), "=r"(r3) : "r"(addr));
}
__device__ __forceinline__ uint32_t smem_u32(const void* p) {
    return (uint32_t)__cvta_generic_to_shared(p);
}

#define CP16(dst, src) \
    asm volatile("cp.async.cg.shared.global [%0], [%1], 16;" :: "r"(dst), "l"(src))
#define CP16Z(dst, src, sz) \
    asm volatile("cp.async.cg.shared.global [%0], [%1], 16, %2;" :: "r"(dst), "l"(src), "r"(sz))

// ---------------------------------------------------------------------------
// Weight prepack: B[K][N] (row-major, per expert) -> hi/lo [N][K/2] uint32
// ---------------------------------------------------------------------------
__global__ void prepack_kernel(const float* __restrict__ B,
                               uint32_t* __restrict__ Hi, uint32_t* __restrict__ Lo,
                               int K, int N)
{
    const int e = blockIdx.z;
    B  += (size_t)e * K * N;
    Hi += (size_t)e * N * (K / 2);
    Lo += (size_t)e * N * (K / 2);

    __shared__ float tile[64][33];
    const int tid = threadIdx.x;
    const int k0 = blockIdx.y * 64;
    const int n0 = blockIdx.x * 32;

#pragma unroll
    for (int i = 0; i < 8; i++) {
        const int row = i * 8 + (tid >> 5);
        const int col = tid & 31;
        tile[row][col] = B[(size_t)(k0 + row) * N + n0 + col];
    }
    __syncthreads();

#pragma unroll
    for (int j = 0; j < 4; j++) {
        const int nl = (tid >> 5) * 4 + j;
        const int kp = tid & 31;
        const float x0 = tile[2 * kp][nl];
        const float x1 = tile[2 * kp + 1][nl];
        const float h0 = bf16_rt(x0), h1 = bf16_rt(x1);
        const size_t o = (size_t)(n0 + nl) * (K / 2) + k0 / 2 + kp;
        Hi[o] = pack_bf16x2(h0, h1);
        Lo[o] = pack_bf16x2(x0 - h0, x1 - h1);
    }
}

// ---------------------------------------------------------------------------
// Activation convert: fp32 [rows][K] -> hi/lo packed [rows][K/2]
// ---------------------------------------------------------------------------
__global__ void convert_kernel(const float* __restrict__ X,
                               uint32_t* __restrict__ Hi, uint32_t* __restrict__ Lo,
                               int total_pairs)
{
    int i = blockIdx.x * blockDim.x + threadIdx.x;
    if (i >= total_pairs) return;
    float2 v = reinterpret_cast<const float2*>(X)[i];
    float h0 = bf16_rt(v.x), h1 = bf16_rt(v.y);
    Hi[i] = pack_bf16x2(h0, h1);
    Lo[i] = pack_bf16x2(v.x - h0, v.y - h1);
}

// ---------------------------------------------------------------------------
// bf16-split tensor GEMM: 256x128 CTA tile, K-tile 32, 256 threads,
// 8 warps of 64x64, double-buffered pure cp.async staging (both operands
// prepacked hi/lo bf16x2), ldmatrix fragments.
// Smem per stage: AsH[256][20] AsL[256][20] BsH[128][20] BsL[128][20]
// ---------------------------------------------------------------------------
#define RSTRIDE 80                        // bytes per smem row (20 u32)
#define OFF_AL  (256 * RSTRIDE)           // 20480
#define OFF_BH  (2 * 256 * RSTRIDE)       // 40960
#define OFF_BL  (OFF_BH + 128 * RSTRIDE)  // 51200
#define STAGE_B (OFF_BL + 128 * RSTRIDE)  // 61440
#define GEMM_SMEM (2 * STAGE_B)           // 122880

template<bool GROUPED, bool GATHER, bool DO_GELU, bool OUT_PAIR>
__global__ __launch_bounds__(256, 1)
void mma_gemm(const uint32_t* __restrict__ AH, const uint32_t* __restrict__ AL,
              const uint32_t* __restrict__ BH, const uint32_t* __restrict__ BL,
              const float* __restrict__ biasAll,
              float* __restrict__ CoutF,
              uint32_t* __restrict__ CoutH, uint32_t* __restrict__ CoutL,
              int M, int N, int K)
{
    extern __shared__ __align__(16) uint32_t smem[];

    int rows = M, segBase = 0, m0, n0;
    const float* bias;
    if (GROUPED) {
        const int e = blockIdx.y;
        rows    = g_counts[e];
        m0      = blockIdx.x * 256;
        if (m0 >= rows) return;
        segBase = g_offsets[e];
        n0      = blockIdx.z * 128;
        BH     += (size_t)e * N * (K / 2);
        BL     += (size_t)e * N * (K / 2);
        bias    = biasAll + (size_t)e * N;
    } else {
        m0   = blockIdx.y * 256;
        n0   = blockIdx.x * 128;
        bias = biasAll;
    }

    const int tid  = threadIdx.x;
    const int lane = tid & 31;
    const int wid  = tid >> 5;
    const int g    = lane >> 2;
    const int tig  = lane & 3;
    const int wm   = (wid & 3) * 64;     // 4 m-slots
    const int wn   = (wid >> 2) * 64;    // 2 n-slots

    const uint32_t base = smem_u32(smem);
    const int Kp = K / 2;

    // ---- staging: A row = tid (4 chunks hi + 4 lo); B row = tid>>1, half (tid&1)
    uint32_t aSz = 16;
    const uint32_t* aPH;
    const uint32_t* aPL;
    {
        int gr = m0 + tid, row = 0;
        if (GROUPED) {
            if (gr < rows) row = GATHER ? g_perm[segBase + gr] : (segBase + gr);
            else           aSz = 0;
        } else row = gr;
        aPH = AH + (size_t)row * Kp;
        aPL = AL + (size_t)row * Kp;
    }
    const uint32_t* bPH = BH + (size_t)(n0 + (tid >> 1)) * Kp + (tid & 1) * 8;
    const uint32_t* bPL = BL + (size_t)(n0 + (tid >> 1)) * Kp + (tid & 1) * 8;
    const uint32_t a_dst = tid * RSTRIDE;
    const uint32_t b_dst = OFF_BH + (tid >> 1) * RSTRIDE + (tid & 1) * 32;

    // ---- ldmatrix per-lane addresses (stage-local byte offsets)
    const uint32_t a_frag = (wm + (lane & 15)) * RSTRIDE + (lane >> 4) * 16;
    const uint32_t b_frag = OFF_BH + (wn + ((lane >> 4) & 1) * 8 + (lane & 7)) * RSTRIDE
                            + ((lane >> 3) & 1) * 16;

    float acc[4][8][4];
#pragma unroll
    for (int m = 0; m < 4; m++)
#pragma unroll
        for (int n = 0; n < 8; n++)
#pragma unroll
            for (int i = 0; i < 4; i++) acc[m][n][i] = 0.0f;

    const int KT = K / 32;

    auto load_tile = [&](int kt, int s) {
        const uint32_t sb = base + (uint32_t)s * STAGE_B;
        const uint32_t ko = (uint32_t)kt * 16;
#pragma unroll
        for (int c = 0; c < 4; c++) {
            CP16Z(sb + a_dst + c * 16,          aPH + ko + c * 4, aSz);
            CP16Z(sb + OFF_AL + a_dst + c * 16, aPL + ko + c * 4, aSz);
        }
        CP16(sb + b_dst,                          bPH + ko);
        CP16(sb + b_dst + 16,                     bPH + ko + 4);
        CP16(sb + (OFF_BL - OFF_BH) + b_dst,      bPL + ko);
        CP16(sb + (OFF_BL - OFF_BH) + b_dst + 16, bPL + ko + 4);
        asm volatile("cp.async.commit_group;");
    };

    load_tile(0, 0);
    if (KT > 1) load_tile(1, 1);

    for (int kt = 0; kt < KT; kt++) {
        const int s = kt & 1;
        if (kt + 1 < KT) asm volatile("cp.async.wait_group 1;" ::: "memory");
        else             asm volatile("cp.async.wait_group 0;" ::: "memory");
        __syncthreads();

        const uint32_t sb = base + (uint32_t)s * STAGE_B;
#pragma unroll
        for (int ks = 0; ks < 2; ks++) {
            const uint32_t ksb = ks * 32;
            uint32_t bHf[8][2], bLf[8][2];
#pragma unroll
            for (int nb = 0; nb < 4; nb++) {
                const uint32_t bo = sb + b_frag + nb * 16 * RSTRIDE + ksb;
                ldsm_x4(bHf[2*nb][0], bHf[2*nb][1], bHf[2*nb+1][0], bHf[2*nb+1][1], bo);
                ldsm_x4(bLf[2*nb][0], bLf[2*nb][1], bLf[2*nb+1][0], bLf[2*nb+1][1],
                        bo + (OFF_BL - OFF_BH));
            }
#pragma unroll
            for (int m = 0; m < 4; m++) {
                const uint32_t ao = sb + a_frag + m * 16 * RSTRIDE + ksb;
                uint32_t aHf[4], aLf[4];
                ldsm_x4(aHf[0], aHf[1], aHf[2], aHf[3], ao);
                ldsm_x4(aLf[0], aLf[1], aLf[2], aLf[3], ao + OFF_AL);
#pragma unroll
                for (int n = 0; n < 8; n++) {
                    mma_bf16(acc[m][n], aHf, bHf[n]);
                    mma_bf16(acc[m][n], aHf, bLf[n]);
                    mma_bf16(acc[m][n], aLf, bHf[n]);
                }
            }
        }
        __syncthreads();
        if (kt + 2 < KT) load_tile(kt + 2, s);
    }

    // ---- epilogue ----
#pragma unroll
    for (int n = 0; n < 8; n++) {
        const int col = n0 + wn + n * 8 + 2 * tig;
        const float b0 = bias[col];
        const float b1 = bias[col + 1];
#pragma unroll
        for (int m = 0; m < 4; m++) {
            const int r0 = wm + m * 16 + g;
            float v00 = acc[m][n][0] + b0;
            float v01 = acc[m][n][1] + b1;
            float v10 = acc[m][n][2] + b0;
            float v11 = acc[m][n][3] + b1;
            if (DO_GELU) {
                v00 = gelu_exact(v00); v01 = gelu_exact(v01);
                v10 = gelu_exact(v10); v11 = gelu_exact(v11);
            }
            const bool ok0 = !GROUPED || (m0 + r0 < rows);
            const bool ok1 = !GROUPED || (m0 + r0 + 8 < rows);
            const size_t gr0 = (size_t)(segBase + m0 + r0);
            const size_t gr1 = gr0 + 8;
            if (OUT_PAIR) {
                const int ci = col >> 1;
                if (ok0) {
                    float h0 = bf16_rt(v00), h1 = bf16_rt(v01);
                    CoutH[gr0 * (N / 2) + ci] = pack_bf16x2(h0, h1);
                    CoutL[gr0 * (N / 2) + ci] = pack_bf16x2(v00 - h0, v01 - h1);
                }
                if (ok1) {
                    float h0 = bf16_rt(v10), h1 = bf16_rt(v11);
                    CoutH[gr1 * (N / 2) + ci] = pack_bf16x2(h0, h1);
                    CoutL[gr1 * (N / 2) + ci] = pack_bf16x2(v10 - h0, v11 - h1);
                }
            } else {
                if (ok0)
                    *reinterpret_cast<float2*>(CoutF + gr0 * N + col) = make_float2(v00, v01);
                if (ok1)
                    *reinterpret_cast<float2*>(CoutF + gr1 * N + col) = make_float2(v10, v11);
            }
        }
    }
}

// ---------------------------------------------------------------------------
// Routing: one warp per sub-token; h reconstructed from hi/lo pairs.
// ---------------------------------------------------------------------------
__global__ void routing_kernel(const float* __restrict__ emb)
{
    const int warp = (blockIdx.x * blockDim.x + threadIdx.x) >> 5;
    const int lane = threadIdx.x & 31;
    if (warp >= NSUB) return;

    const uint32_t* hH = g_hH + (size_t)warp * (HD / 2);
    const uint32_t* hL = g_hL + (size_t)warp * (HD / 2);
    float2 a0 = unpack_bf16x2(hH[lane]);
    float2 l0 = unpack_bf16x2(hL[lane]);
    float2 a1 = unpack_bf16x2(hH[lane + 32]);
    float2 l1 = unpack_bf16x2(hL[lane + 32]);
    const float t0 = a0.x + l0.x, t1 = a0.y + l0.y;
    const float t2 = a1.x + l1.x, t3 = a1.y + l1.y;
    const int k0 = 2 * lane, k1 = 2 * lane + 64;

    float logits[NE];
#pragma unroll
    for (int e = 0; e < NE; e++) {
        float p = t0 * emb[(k0    ) * NE + e]
                + t1 * emb[(k0 + 1) * NE + e]
                + t2 * emb[(k1    ) * NE + e]
                + t3 * emb[(k1 + 1) * NE + e];
#pragma unroll
        for (int s = 16; s > 0; s >>= 1) p += __shfl_xor_sync(0xffffffffu, p, s);
        logits[e] = p;
    }

    float mx = logits[0];
#pragma unroll
    for (int e = 1; e < NE; e++) mx = fmaxf(mx, logits[e]);
    float sum = 0.0f;
#pragma unroll
    for (int e = 0; e < NE; e++) { logits[e] = expf(logits[e] - mx); sum += logits[e]; }
    const float inv = 1.0f / sum;

    int i0 = 0; float v0 = logits[0];
#pragma unroll
    for (int e = 1; e < NE; e++) if (logits[e] > v0) { v0 = logits[e]; i0 = e; }
    int i1 = -1; float v1 = -1.0f;
#pragma unroll
    for (int e = 0; e < NE; e++) if (e != i0 && logits[e] > v1) { v1 = logits[e]; i1 = e; }

    if (lane == 0) {
        g_topi[2 * warp + 0] = i0;
        g_topi[2 * warp + 1] = i1;
        g_topw[2 * warp + 0] = v0 * inv;
        g_topw[2 * warp + 1] = v1 * inv;
    }
}

// ---------------------------------------------------------------------------
// Routing bookkeeping (block-aggregated atomics)
// ---------------------------------------------------------------------------
__global__ void zero_counts() {
    int i = threadIdx.x;
    if (i < NE) { g_counts[i] = 0; g_cursor[i] = 0; }
}
__global__ void hist_kernel() {
    __shared__ int loc[NE];
    if (threadIdx.x < NE) loc[threadIdx.x] = 0;
    __syncthreads();
    int i = blockIdx.x * blockDim.x + threadIdx.x;
    atomicAdd(&loc[g_topi[i]], 1);
    __syncthreads();
    if (threadIdx.x < NE && loc[threadIdx.x])
        atomicAdd(&g_counts[threadIdx.x], loc[threadIdx.x]);
}
__global__ void scan_kernel() {
    int s = 0;
    for (int e = 0; e < NE; e++) { g_offsets[e] = s; s += g_counts[e]; }
    g_offsets[NE] = s;
}
__global__ void scatter_kernel() {
    __shared__ int bcnt[NE];
    __shared__ int bbase[NE];
    if (threadIdx.x < NE) bcnt[threadIdx.x] = 0;
    __syncthreads();

    const int i    = blockIdx.x * blockDim.x + threadIdx.x;
    const int lane = threadIdx.x & 31;
    const int e    = g_topi[i];

    unsigned mask   = __match_any_sync(0xffffffffu, e);
    const int leader = __ffs(mask) - 1;
    const int lrank  = __popc(mask & ((1u << lane) - 1));
    int wbase = 0;
    if (lane == leader) wbase = atomicAdd(&bcnt[e], __popc(mask));
    wbase = __shfl_sync(0xffffffffu, wbase, leader);
    __syncthreads();

    if (threadIdx.x < NE)
        bbase[threadIdx.x] = bcnt[threadIdx.x]
            ? atomicAdd(&g_cursor[threadIdx.x], bcnt[threadIdx.x]) : 0;
    __syncthreads();

    const int slot = g_offsets[e] + bbase[e] + wbase + lrank;
    g_perm[slot] = i >> 1;
    g_pos[i] = slot;
}

// ---------------------------------------------------------------------------
// Combine: comb pairs (hi/lo bf16x2) from fp32 eo
// ---------------------------------------------------------------------------
__global__ void combine_kernel() {
    int idx = blockIdx.x * blockDim.x + threadIdx.x;   // over NSUB*(HD/2)
    int t = idx >> 6;
    int j = idx & 63;
    float w0 = g_topw[2 * t + 0];
    float w1 = g_topw[2 * t + 1];
    int   s0 = g_pos [2 * t + 0];
    int   s1 = g_pos [2 * t + 1];
    float2 a = reinterpret_cast<const float2*>(g_eo)[(size_t)s0 * (HD / 2) + j];
    float2 b = reinterpret_cast<const float2*>(g_eo)[(size_t)s1 * (HD / 2) + j];
    float c0 = w0 * a.x + w1 * b.x;
    float c1 = w0 * a.y + w1 * b.y;
    float h0 = bf16_rt(c0), h1 = bf16_rt(c1);
    g_cH[idx] = pack_bf16x2(h0, h1);
    g_cL[idx] = pack_bf16x2(c0 - h0, c1 - h1);
}

// ---------------------------------------------------------------------------
// Launch
// ---------------------------------------------------------------------------
extern "C" void kernel_launch(void* const* d_in, const int* in_sizes, int n_in,
                              void* d_out, int out_size)
{
    (void)in_sizes; (void)n_in; (void)out_size;
    const float* x   = (const float*)d_in[0];
    const float* Wm  = (const float*)d_in[1];
    const float* bm  = (const float*)d_in[2];
    const float* emb = (const float*)d_in[3];
    const float* W1  = (const float*)d_in[4];
    const float* b1  = (const float*)d_in[5];
    const float* W2  = (const float*)d_in[6];
    const float* b2  = (const float*)d_in[7];
    const float* Wo  = (const float*)d_in[8];
    const float* bo  = (const float*)d_in[9];
    float* out = (float*)d_out;

    float* eo_p;
    cudaGetSymbolAddress((void**)&eo_p, g_eo);
    uint32_t *xH,*xL,*hH,*hL,*mH,*mL,*cH,*cL;
    cudaGetSymbolAddress((void**)&xH, g_xH); cudaGetSymbolAddress((void**)&xL, g_xL);
    cudaGetSymbolAddress((void**)&hH, g_hH); cudaGetSymbolAddress((void**)&hL, g_hL);
    cudaGetSymbolAddress((void**)&mH, g_mH); cudaGetSymbolAddress((void**)&mL, g_mL);
    cudaGetSymbolAddress((void**)&cH, g_cH); cudaGetSymbolAddress((void**)&cL, g_cL);
    uint32_t *WmH,*WmL,*W1H,*W1L,*W2H,*W2L,*WoH,*WoL;
    cudaGetSymbolAddress((void**)&WmH, g_WmH); cudaGetSymbolAddress((void**)&WmL, g_WmL);
    cudaGetSymbolAddress((void**)&W1H, g_W1H); cudaGetSymbolAddress((void**)&W1L, g_W1L);
    cudaGetSymbolAddress((void**)&W2H, g_W2H); cudaGetSymbolAddress((void**)&W2L, g_W2L);
    cudaGetSymbolAddress((void**)&WoH, g_WoH); cudaGetSymbolAddress((void**)&WoL, g_WoL);

    cudaFuncSetAttribute(mma_gemm<false,false,false,true>,
                         cudaFuncAttributeMaxDynamicSharedMemorySize, GEMM_SMEM);
    cudaFuncSetAttribute(mma_gemm<true,true,true,true>,
                         cudaFuncAttributeMaxDynamicSharedMemorySize, GEMM_SMEM);
    cudaFuncSetAttribute(mma_gemm<true,false,false,false>,
                         cudaFuncAttributeMaxDynamicSharedMemorySize, GEMM_SMEM);
    cudaFuncSetAttribute(mma_gemm<false,false,false,false>,
                         cudaFuncAttributeMaxDynamicSharedMemorySize, GEMM_SMEM);

    // 0) prepack weights + convert x
    prepack_kernel<<<dim3(DIM/32, DIM/64, 1),  256>>>(Wm, WmH, WmL, DIM, DIM);
    prepack_kernel<<<dim3(II/32,  HD/64,  NE), 256>>>(W1, W1H, W1L, HD, II);
    prepack_kernel<<<dim3(HD/32,  II/64,  NE), 256>>>(W2, W2H, W2L, II, HD);
    prepack_kernel<<<dim3(DIM/32, DIM/64, 1),  256>>>(Wo, WoH, WoL, DIM, DIM);
    convert_kernel<<<(NTOK * DIM / 2 + 255) / 256, 256>>>(x, xH, xL, NTOK * DIM / 2);

    // 1) h = x @ Wm + bm  -> hi/lo pairs
    mma_gemm<false,false,false,true><<<dim3(DIM/128, NTOK/256), 256, GEMM_SMEM>>>(
        xH, xL, WmH, WmL, bm, nullptr, hH, hL, NTOK, DIM, DIM);

    // 2) routing
    routing_kernel<<<NSUB / 8, 256>>>(emb);

    // 3) expert bookkeeping
    zero_counts<<<1, 32>>>();
    hist_kernel<<<NPAIR / 256, 256>>>();
    scan_kernel<<<1, 1>>>();
    scatter_kernel<<<NPAIR / 256, 256>>>();

    // 4) hmid = gelu(t @ W1[e] + b1[e]) -> hi/lo pairs   K=128, N=512
    mma_gemm<true,true,true,true><<<dim3(NPAIR/256, NE, II/128), 256, GEMM_SMEM>>>(
        hH, hL, W1H, W1L, b1, nullptr, mH, mL, 0, II, HD);

    // 5) eo = hmid @ W2[e] + b2[e]  (fp32)   K=512, N=128
    mma_gemm<true,false,false,false><<<dim3(NPAIR/256, NE, HD/128), 256, GEMM_SMEM>>>(
        mH, mL, W2H, W2L, b2, eo_p, nullptr, nullptr, 0, HD, II);

    // 6) combine -> comb hi/lo pairs
    combine_kernel<<<(NSUB * HD / 2) / 256, 256>>>();

    // 7) out = comb @ Wo + bo  (fp32)
    mma_gemm<false,false,false,false><<<dim3(DIM/128, NTOK/256), 256, GEMM_SMEM>>>(
        cH, cL, WoH, WoL, bo, out, nullptr, nullptr, NTOK, DIM, DIM);
}

// round 9
// speedup vs baseline: 1.4701x; 1.4701x over previous
#include <cuda_runtime.h>
#include <cuda_bf16.h>
#include <math.h>
#include <stdint.h>

// ---------------------------------------------------------------------------
// Problem constants
// ---------------------------------------------------------------------------
#define BSZ   4
#define LEN   2048
#define DIM   1024
#define NH    8
#define NE    16
#define TOPK  2
#define HD    128
#define II    512
#define NTOK  (BSZ*LEN)    // 8192
#define NSUB  (NTOK*NH)    // 65536
#define NPAIR (NSUB*TOPK)  // 131072

// ---------------------------------------------------------------------------
// Device scratch
// ---------------------------------------------------------------------------
__device__ float g_h   [(size_t)NTOK * DIM];
__device__ float g_comb[(size_t)NTOK * DIM];
__device__ float g_hmid[(size_t)NPAIR * II];
__device__ float g_eo  [(size_t)NPAIR * HD];
__device__ int   g_topi[NPAIR];
__device__ float g_topw[NPAIR];
__device__ int   g_perm[NPAIR];
__device__ int   g_pos [NPAIR];
__device__ int   g_counts[NE];
__device__ int   g_cursor[NE];
__device__ int   g_offsets[NE + 1];

// Prepacked weights: hi/lo bf16x2 (packed along k), transposed to [N][K/2]
__device__ uint32_t g_WmH[(size_t)DIM * DIM / 2];
__device__ uint32_t g_WmL[(size_t)DIM * DIM / 2];
__device__ uint32_t g_W1H[(size_t)NE * II * HD / 2];
__device__ uint32_t g_W1L[(size_t)NE * II * HD / 2];
__device__ uint32_t g_W2H[(size_t)NE * HD * II / 2];
__device__ uint32_t g_W2L[(size_t)NE * HD * II / 2];
__device__ uint32_t g_WoH[(size_t)DIM * DIM / 2];
__device__ uint32_t g_WoL[(size_t)DIM * DIM / 2];

__device__ __forceinline__ float gelu_exact(float x) {
    return 0.5f * x * (1.0f + erff(x * 0.70710678118654752440f));
}
__device__ __forceinline__ uint32_t pack_bf16x2(float e0, float e1) {
    uint32_t r;
    asm("cvt.rn.bf16x2.f32 %0, %1, %2;" : "=r"(r) : "f"(e1), "f"(e0));
    return r;
}
__device__ __forceinline__ float bf16_rt(float x) {
    return __bfloat162float(__float2bfloat16(x));
}
__device__ __forceinline__ void mma_bf16(float* d, const uint32_t* a, const uint32_t* b) {
    asm volatile(
        "mma.sync.aligned.m16n8k16.row.col.f32.bf16.bf16.f32 "
        "{%0,%1,%2,%3}, {%4,%5,%6,%7}, {%8,%9}, {%0,%1,%2,%3};\n"
        : "+f"(d[0]), "+f"(d[1]), "+f"(d[2]), "+f"(d[3])
        : "r"(a[0]), "r"(a[1]), "r"(a[2]), "r"(a[3]), "r"(b[0]), "r"(b[1]));
}
__device__ __forceinline__ void ldsm_x4(uint32_t& r0, uint32_t& r1,
                                        uint32_t& r2, uint32_t& r3, uint32_t addr) {
    asm volatile("ldmatrix.sync.aligned.m8n8.x4.shared.b16 {%0,%1,%2,%3}, [%4];"
                 : "=r"(r0), "=r"(r1), "=r"(r2), "=r"(r3) : "r"(addr));
}
__device__ __forceinline__ uint32_t smem_u32(const void* p) {
    return (uint32_t)__cvta_generic_to_shared(p);
}

#define CP16(dst, src) \
    asm volatile("cp.async.cg.shared.global [%0], [%1], 16;" :: "r"(dst), "l"(src))

// ---------------------------------------------------------------------------
// Weight prepack: B[K][N] (row-major, per expert) -> hi/lo [N][K/2] uint32
// ---------------------------------------------------------------------------
__global__ void prepack_kernel(const float* __restrict__ B,
                               uint32_t* __restrict__ Hi, uint32_t* __restrict__ Lo,
                               int K, int N)
{
    const int e = blockIdx.z;
    B  += (size_t)e * K * N;
    Hi += (size_t)e * N * (K / 2);
    Lo += (size_t)e * N * (K / 2);

    __shared__ float tile[64][33];
    const int tid = threadIdx.x;
    const int k0 = blockIdx.y * 64;
    const int n0 = blockIdx.x * 32;

#pragma unroll
    for (int i = 0; i < 8; i++) {
        const int row = i * 8 + (tid >> 5);
        const int col = tid & 31;
        tile[row][col] = B[(size_t)(k0 + row) * N + n0 + col];
    }
    __syncthreads();

#pragma unroll
    for (int j = 0; j < 4; j++) {
        const int nl = (tid >> 5) * 4 + j;
        const int kp = tid & 31;
        const float x0 = tile[2 * kp][nl];
        const float x1 = tile[2 * kp + 1][nl];
        const float h0 = bf16_rt(x0), h1 = bf16_rt(x1);
        const size_t o = (size_t)(n0 + nl) * (K / 2) + k0 / 2 + kp;
        Hi[o] = pack_bf16x2(h0, h1);
        Lo[o] = pack_bf16x2(x0 - h0, x1 - h1);
    }
}

// ---------------------------------------------------------------------------
// bf16-split tensor GEMM (R6: B double-buffer + A reg prefetch).
// Block 128x128, K-tile 32, 256 threads (8 warps, 64x32 warp tile).
// Dynamic smem, 6 tiles of [128][20] uint32:
//   tile 0: AsH   tile 1: AsL
//   tile 2+2s: BsH stage s   tile 3+2s: BsL stage s
// ---------------------------------------------------------------------------
#define TSTRIDE 20
#define TILE_B  (128 * TSTRIDE * 4)       // 10240 bytes
#define SMEM_BYTES (6 * TILE_B)           // 61440

template<bool GROUPED, bool GATHER, bool DO_GELU>
__global__ __launch_bounds__(256, 2)
void mma_gemm(const float* __restrict__ Asrc,
              const uint32_t* __restrict__ BpH, const uint32_t* __restrict__ BpL,
              const float* __restrict__ biasAll, float* __restrict__ Cout,
              int M, int N, int K)
{
    extern __shared__ __align__(16) uint32_t smem[];

    int rows = M, segBase = 0, m0, n0;
    const float* bias;
    if (GROUPED) {
        const int e = blockIdx.y;
        rows    = g_counts[e];
        m0      = blockIdx.x * 128;
        if (m0 >= rows) return;
        segBase = g_offsets[e];
        n0      = blockIdx.z * 128;
        BpH    += (size_t)e * N * (K / 2);
        BpL    += (size_t)e * N * (K / 2);
        bias    = biasAll + (size_t)e * N;
    } else {
        m0   = blockIdx.y * 128;
        n0   = blockIdx.x * 128;
        bias = biasAll;
    }

    const int tid  = threadIdx.x;
    const int lane = tid & 31;
    const int wid  = tid >> 5;
    const int g    = lane >> 2;
    const int tig  = lane & 3;
    const int wm   = (wid & 1) * 64;
    const int wn   = (wid >> 1) * 32;

    const uint32_t base = smem_u32(smem);

    // A loads: thread covers 4 rows, float4 at col (tid&7)*4
    const int acol = (tid & 7) * 4;
    const float* arow[4];
    bool aval[4];
#pragma unroll
    for (int v = 0; v < 4; v++) {
        const int r  = v * 32 + (tid >> 3);
        const int gr = m0 + r;
        if (GROUPED) {
            aval[v] = (gr < rows);
            int row = 0;
            if (aval[v]) row = GATHER ? g_perm[segBase + gr] : (segBase + gr);
            arow[v] = Asrc + (size_t)row * K + acol;
        } else {
            aval[v] = true;
            arow[v] = Asrc + (size_t)gr * K + acol;
        }
    }
    // A smem store addresses (uint2 at [r][acol>>1], tiles 0 and 1)
    const uint32_t a_st = base + (((tid >> 3) * TSTRIDE) + (acol >> 1)) * 4;

    // B loads: thread covers col = tid>>1, 8 kpairs starting (tid&1)*8
    const int bcol  = tid >> 1;
    const int bkp   = (tid & 1) * 8;
    const uint32_t* bptrH = BpH + (size_t)(n0 + bcol) * (K / 2) + bkp;
    const uint32_t* bptrL = BpL + (size_t)(n0 + bcol) * (K / 2) + bkp;
    const uint32_t b_st = (bcol * TSTRIDE + bkp) * 4;

    // ldmatrix per-lane addresses (byte offsets)
    const uint32_t a_off = (((wm + (lane & 15)) * TSTRIDE) + ((lane >> 4) * 4)) * 4;
    const uint32_t aH_addr = base + a_off;
    const uint32_t aL_addr = base + TILE_B + a_off;
    const uint32_t b_off = (((wn + ((lane >> 4) & 1) * 8 + (lane & 7)) * TSTRIDE)
                            + (((lane >> 3) & 1) * 4)) * 4;

    float acc[4][4][4];
#pragma unroll
    for (int m = 0; m < 4; m++)
#pragma unroll
        for (int n = 0; n < 4; n++)
#pragma unroll
            for (int i = 0; i < 4; i++) acc[m][n][i] = 0.0f;

    const int KT = K / 32;

    // ---- preloop: A tile 0 -> regs -> convert -> STS; B tile 0 cp.async ----
    float4 areg[4];
#pragma unroll
    for (int v = 0; v < 4; v++) {
        areg[v] = make_float4(0.f, 0.f, 0.f, 0.f);
        if (aval[v]) areg[v] = *reinterpret_cast<const float4*>(arow[v]);
    }
#pragma unroll
    for (int v = 0; v < 4; v++) {
        const float hx = bf16_rt(areg[v].x), hy = bf16_rt(areg[v].y);
        const float hz = bf16_rt(areg[v].z), hw = bf16_rt(areg[v].w);
        uint2 hv, lv;
        hv.x = pack_bf16x2(hx, hy);
        hv.y = pack_bf16x2(hz, hw);
        lv.x = pack_bf16x2(areg[v].x - hx, areg[v].y - hy);
        lv.y = pack_bf16x2(areg[v].z - hz, areg[v].w - hw);
        const uint32_t d = a_st + v * 32 * TSTRIDE * 4;
        asm volatile("st.shared.v2.b32 [%0], {%1,%2};" :: "r"(d), "r"(hv.x), "r"(hv.y));
        asm volatile("st.shared.v2.b32 [%0], {%1,%2};"
                     :: "r"(d + TILE_B), "r"(lv.x), "r"(lv.y));
    }
    {
        const uint32_t dB = base + 2 * TILE_B + b_st;
        CP16(dB,                   bptrH);
        CP16(dB + 16,              bptrH + 4);
        CP16(dB + TILE_B,          bptrL);
        CP16(dB + TILE_B + 16,     bptrL + 4);
        asm volatile("cp.async.commit_group;");
    }

    for (int kt = 0; kt < KT; kt++) {
        const int s = kt & 1;
        const bool more = (kt + 1 < KT);
        if (more) {
            // prefetch next A tile into regs (consumed after compute)
            const int ko = (kt + 1) * 32;
#pragma unroll
            for (int v = 0; v < 4; v++) {
                areg[v] = make_float4(0.f, 0.f, 0.f, 0.f);
                if (aval[v]) areg[v] = *reinterpret_cast<const float4*>(arow[v] + ko);
            }
            // next B tile into stage s^1
            const int kpo = (kt + 1) * 16;
            const uint32_t dB = base + (2 + 2 * (s ^ 1)) * TILE_B + b_st;
            CP16(dB,               bptrH + kpo);
            CP16(dB + 16,          bptrH + kpo + 4);
            CP16(dB + TILE_B,      bptrL + kpo);
            CP16(dB + TILE_B + 16, bptrL + kpo + 4);
            asm volatile("cp.async.commit_group;");
            asm volatile("cp.async.wait_group 1;" ::: "memory");
        } else {
            asm volatile("cp.async.wait_group 0;" ::: "memory");
        }
        __syncthreads();

        const uint32_t bH_addr = base + (2 + 2 * s) * TILE_B + b_off;
        const uint32_t bL_addr = bH_addr + TILE_B;

#pragma unroll
        for (int ks = 0; ks < 2; ks++) {
            const uint32_t ksb = ks * 32;
            uint32_t bH[4][2], bL[4][2];
            ldsm_x4(bH[0][0], bH[0][1], bH[1][0], bH[1][1], bH_addr + ksb);
            ldsm_x4(bH[2][0], bH[2][1], bH[3][0], bH[3][1], bH_addr + ksb + 16 * TSTRIDE * 4);
            ldsm_x4(bL[0][0], bL[0][1], bL[1][0], bL[1][1], bL_addr + ksb);
            ldsm_x4(bL[2][0], bL[2][1], bL[3][0], bL[3][1], bL_addr + ksb + 16 * TSTRIDE * 4);
#pragma unroll
            for (int m = 0; m < 4; m++) {
                const uint32_t mb = m * 16 * TSTRIDE * 4;
                uint32_t aH[4], aL[4];
                ldsm_x4(aH[0], aH[1], aH[2], aH[3], aH_addr + mb + ksb);
                ldsm_x4(aL[0], aL[1], aL[2], aL[3], aL_addr + mb + ksb);
#pragma unroll
                for (int n = 0; n < 4; n++) {
                    mma_bf16(acc[m][n], aH, bH[n]);
                    mma_bf16(acc[m][n], aH, bL[n]);
                    mma_bf16(acc[m][n], aL, bH[n]);
                }
            }
        }
        __syncthreads();

        if (more) {
            // convert prefetched A regs -> smem (A tile single-stage)
#pragma unroll
            for (int v = 0; v < 4; v++) {
                const float hx = bf16_rt(areg[v].x), hy = bf16_rt(areg[v].y);
                const float hz = bf16_rt(areg[v].z), hw = bf16_rt(areg[v].w);
                uint2 hv, lv;
                hv.x = pack_bf16x2(hx, hy);
                hv.y = pack_bf16x2(hz, hw);
                lv.x = pack_bf16x2(areg[v].x - hx, areg[v].y - hy);
                lv.y = pack_bf16x2(areg[v].z - hz, areg[v].w - hw);
                const uint32_t d = a_st + v * 32 * TSTRIDE * 4;
                asm volatile("st.shared.v2.b32 [%0], {%1,%2};" :: "r"(d), "r"(hv.x), "r"(hv.y));
                asm volatile("st.shared.v2.b32 [%0], {%1,%2};"
                             :: "r"(d + TILE_B), "r"(lv.x), "r"(lv.y));
            }
        }
    }

    // ---- epilogue ----
#pragma unroll
    for (int n = 0; n < 4; n++) {
        const int col = n0 + wn + n * 8 + 2 * tig;
        const float b0 = bias[col];
        const float b1 = bias[col + 1];
#pragma unroll
        for (int m = 0; m < 4; m++) {
            const int r0 = wm + m * 16 + g;
            float v00 = acc[m][n][0] + b0;
            float v01 = acc[m][n][1] + b1;
            float v10 = acc[m][n][2] + b0;
            float v11 = acc[m][n][3] + b1;
            if (DO_GELU) {
                v00 = gelu_exact(v00); v01 = gelu_exact(v01);
                v10 = gelu_exact(v10); v11 = gelu_exact(v11);
            }
            if (GROUPED) {
                if (m0 + r0 < rows) {
                    float* p = Cout + (size_t)(segBase + m0 + r0) * N + col;
                    *reinterpret_cast<float2*>(p) = make_float2(v00, v01);
                }
                if (m0 + r0 + 8 < rows) {
                    float* p = Cout + (size_t)(segBase + m0 + r0 + 8) * N + col;
                    *reinterpret_cast<float2*>(p) = make_float2(v10, v11);
                }
            } else {
                float* p0 = Cout + (size_t)(m0 + r0) * N + col;
                float* p1 = Cout + (size_t)(m0 + r0 + 8) * N + col;
                *reinterpret_cast<float2*>(p0) = make_float2(v00, v01);
                *reinterpret_cast<float2*>(p1) = make_float2(v10, v11);
            }
        }
    }
}

// ---------------------------------------------------------------------------
// Routing: one warp per sub-token.
// ---------------------------------------------------------------------------
__global__ void routing_kernel(const float* __restrict__ emb)
{
    const int warp = (blockIdx.x * blockDim.x + threadIdx.x) >> 5;
    const int lane = threadIdx.x & 31;
    if (warp >= NSUB) return;

    const float* trow = g_h + (size_t)warp * HD;
    const float tv0 = trow[lane];
    const float tv1 = trow[lane + 32];
    const float tv2 = trow[lane + 64];
    const float tv3 = trow[lane + 96];

    float logits[NE];
#pragma unroll
    for (int e = 0; e < NE; e++) {
        float p = tv0 * emb[(lane      ) * NE + e]
                + tv1 * emb[(lane + 32 ) * NE + e]
                + tv2 * emb[(lane + 64 ) * NE + e]
                + tv3 * emb[(lane + 96 ) * NE + e];
#pragma unroll
        for (int s = 16; s > 0; s >>= 1) p += __shfl_xor_sync(0xffffffffu, p, s);
        logits[e] = p;
    }

    float mx = logits[0];
#pragma unroll
    for (int e = 1; e < NE; e++) mx = fmaxf(mx, logits[e]);
    float sum = 0.0f;
#pragma unroll
    for (int e = 0; e < NE; e++) { logits[e] = expf(logits[e] - mx); sum += logits[e]; }
    const float inv = 1.0f / sum;

    int i0 = 0; float v0 = logits[0];
#pragma unroll
    for (int e = 1; e < NE; e++) if (logits[e] > v0) { v0 = logits[e]; i0 = e; }
    int i1 = -1; float v1 = -1.0f;
#pragma unroll
    for (int e = 0; e < NE; e++) if (e != i0 && logits[e] > v1) { v1 = logits[e]; i1 = e; }

    if (lane == 0) {
        g_topi[2 * warp + 0] = i0;
        g_topi[2 * warp + 1] = i1;
        g_topw[2 * warp + 0] = v0 * inv;
        g_topw[2 * warp + 1] = v1 * inv;
    }
}

// ---------------------------------------------------------------------------
// Routing bookkeeping (block/warp aggregated atomics)
// ---------------------------------------------------------------------------
__global__ void zero_counts() {
    int i = threadIdx.x;
    if (i < NE) { g_counts[i] = 0; g_cursor[i] = 0; }
}
__global__ void hist_kernel() {
    __shared__ int loc[NE];
    if (threadIdx.x < NE) loc[threadIdx.x] = 0;
    __syncthreads();
    const int i    = blockIdx.x * blockDim.x + threadIdx.x;
    const int lane = threadIdx.x & 31;
    const int e    = g_topi[i];
    unsigned mask  = __match_any_sync(0xffffffffu, e);
    if (lane == (__ffs(mask) - 1)) atomicAdd(&loc[e], __popc(mask));
    __syncthreads();
    if (threadIdx.x < NE && loc[threadIdx.x])
        atomicAdd(&g_counts[threadIdx.x], loc[threadIdx.x]);
}
__global__ void scan_kernel() {
    int s = 0;
    for (int e = 0; e < NE; e++) { g_offsets[e] = s; s += g_counts[e]; }
    g_offsets[NE] = s;
}
__global__ void scatter_kernel() {
    __shared__ int bcnt[NE];
    __shared__ int bbase[NE];
    if (threadIdx.x < NE) bcnt[threadIdx.x] = 0;
    __syncthreads();

    const int i    = blockIdx.x * blockDim.x + threadIdx.x;
    const int lane = threadIdx.x & 31;
    const int e    = g_topi[i];

    unsigned mask    = __match_any_sync(0xffffffffu, e);
    const int leader = __ffs(mask) - 1;
    const int lrank  = __popc(mask & ((1u << lane) - 1));
    int wbase = 0;
    if (lane == leader) wbase = atomicAdd(&bcnt[e], __popc(mask));
    wbase = __shfl_sync(0xffffffffu, wbase, leader);
    __syncthreads();

    if (threadIdx.x < NE)
        bbase[threadIdx.x] = bcnt[threadIdx.x]
            ? atomicAdd(&g_cursor[threadIdx.x], bcnt[threadIdx.x]) : 0;
    __syncthreads();

    const int slot = g_offsets[e] + bbase[e] + wbase + lrank;
    g_perm[slot] = i >> 1;
    g_pos[i] = slot;
}

// ---------------------------------------------------------------------------
// Combine: comb[t, :] = w0 * eo[pos0, :] + w1 * eo[pos1, :]  (float4)
// ---------------------------------------------------------------------------
__global__ void combine_kernel() {
    int idx = blockIdx.x * blockDim.x + threadIdx.x;   // over NSUB*(HD/4)
    int t = idx >> 5;
    int j = idx & 31;
    float w0 = g_topw[2 * t + 0];
    float w1 = g_topw[2 * t + 1];
    int   s0 = g_pos [2 * t + 0];
    int   s1 = g_pos [2 * t + 1];
    float4 a = reinterpret_cast<const float4*>(g_eo)[(size_t)s0 * (HD / 4) + j];
    float4 b = reinterpret_cast<const float4*>(g_eo)[(size_t)s1 * (HD / 4) + j];
    float4 c;
    c.x = w0 * a.x + w1 * b.x;
    c.y = w0 * a.y + w1 * b.y;
    c.z = w0 * a.z + w1 * b.z;
    c.w = w0 * a.w + w1 * b.w;
    reinterpret_cast<float4*>(g_comb)[idx] = c;
}

// ---------------------------------------------------------------------------
// Launch
// ---------------------------------------------------------------------------
extern "C" void kernel_launch(void* const* d_in, const int* in_sizes, int n_in,
                              void* d_out, int out_size)
{
    (void)in_sizes; (void)n_in; (void)out_size;
    const float* x   = (const float*)d_in[0];
    const float* Wm  = (const float*)d_in[1];
    const float* bm  = (const float*)d_in[2];
    const float* emb = (const float*)d_in[3];
    const float* W1  = (const float*)d_in[4];
    const float* b1  = (const float*)d_in[5];
    const float* W2  = (const float*)d_in[6];
    const float* b2  = (const float*)d_in[7];
    const float* Wo  = (const float*)d_in[8];
    const float* bo  = (const float*)d_in[9];
    float* out = (float*)d_out;

    float *h_p, *comb_p, *hmid_p, *eo_p;
    cudaGetSymbolAddress((void**)&h_p,    g_h);
    cudaGetSymbolAddress((void**)&comb_p, g_comb);
    cudaGetSymbolAddress((void**)&hmid_p, g_hmid);
    cudaGetSymbolAddress((void**)&eo_p,   g_eo);
    uint32_t *WmH, *WmL, *W1H, *W1L, *W2H, *W2L, *WoH, *WoL;
    cudaGetSymbolAddress((void**)&WmH, g_WmH); cudaGetSymbolAddress((void**)&WmL, g_WmL);
    cudaGetSymbolAddress((void**)&W1H, g_W1H); cudaGetSymbolAddress((void**)&W1L, g_W1L);
    cudaGetSymbolAddress((void**)&W2H, g_W2H); cudaGetSymbolAddress((void**)&W2L, g_W2L);
    cudaGetSymbolAddress((void**)&WoH, g_WoH); cudaGetSymbolAddress((void**)&WoL, g_WoL);

    cudaFuncSetAttribute(mma_gemm<false,false,false>,
                         cudaFuncAttributeMaxDynamicSharedMemorySize, SMEM_BYTES);
    cudaFuncSetAttribute(mma_gemm<true,true,true>,
                         cudaFuncAttributeMaxDynamicSharedMemorySize, SMEM_BYTES);
    cudaFuncSetAttribute(mma_gemm<true,false,false>,
                         cudaFuncAttributeMaxDynamicSharedMemorySize, SMEM_BYTES);

    // 0) prepack weights (transpose + bf16 hi/lo split)
    prepack_kernel<<<dim3(DIM/32, DIM/64, 1),  256>>>(Wm, WmH, WmL, DIM, DIM);
    prepack_kernel<<<dim3(II/32,  HD/64,  NE), 256>>>(W1, W1H, W1L, HD, II);
    prepack_kernel<<<dim3(HD/32,  II/64,  NE), 256>>>(W2, W2H, W2L, II, HD);
    prepack_kernel<<<dim3(DIM/32, DIM/64, 1),  256>>>(Wo, WoH, WoL, DIM, DIM);

    // 1) h = x @ Wm + bm
    mma_gemm<false,false,false><<<dim3(DIM/128, NTOK/128), 256, SMEM_BYTES>>>(
        x, WmH, WmL, bm, h_p, NTOK, DIM, DIM);

    // 2) routing
    routing_kernel<<<NSUB / 16, 512>>>(emb);

    // 3) expert bookkeeping
    zero_counts<<<1, 32>>>();
    hist_kernel<<<NPAIR / 256, 256>>>();
    scan_kernel<<<1, 1>>>();
    scatter_kernel<<<NPAIR / 256, 256>>>();

    // 4) hmid = gelu(t @ W1[e] + b1[e])   K=128, N=512 (gathered A)
    mma_gemm<true,true,true><<<dim3(NPAIR/128, NE, II/128), 256, SMEM_BYTES>>>(
        h_p, W1H, W1L, b1, hmid_p, 0, II, HD);

    // 5) eo = hmid @ W2[e] + b2[e]        K=512, N=128
    mma_gemm<true,false,false><<<dim3(NPAIR/128, NE, HD/128), 256, SMEM_BYTES>>>(
        hmid_p, W2H, W2L, b2, eo_p, 0, HD, II);

    // 6) combine
    combine_kernel<<<(NSUB * HD / 4) / 256, 256>>>();

    // 7) out = comb @ Wo + bo
    mma_gemm<false,false,false><<<dim3(DIM/128, NTOK/128), 256, SMEM_BYTES>>>(
        comb_p, WoH, WoL, bo, out, NTOK, DIM, DIM);
}

// round 10
// speedup vs baseline: 1.4906x; 1.0139x over previous
#include <cuda_runtime.h>
#include <cuda_bf16.h>
#include <math.h>
#include <stdint.h>

// ---------------------------------------------------------------------------
// Problem constants
// ---------------------------------------------------------------------------
#define BSZ   4
#define LEN   2048
#define DIM   1024
#define NH    8
#define NE    16
#define TOPK  2
#define HD    128
#define II    512
#define NTOK  (BSZ*LEN)    // 8192
#define NSUB  (NTOK*NH)    // 65536
#define NPAIR (NSUB*TOPK)  // 131072

// ---------------------------------------------------------------------------
// Device scratch
// ---------------------------------------------------------------------------
__device__ float g_h   [(size_t)NTOK * DIM];
__device__ float g_comb[(size_t)NTOK * DIM];
__device__ float g_hmid[(size_t)NPAIR * II];
__device__ float g_eo  [(size_t)NPAIR * HD];
__device__ int   g_topi[NPAIR];
__device__ float g_topw[NPAIR];
__device__ int   g_perm[NPAIR];
__device__ int   g_pos [NPAIR];
__device__ int   g_counts[NE];
__device__ int   g_cursor[NE];
__device__ int   g_offsets[NE + 1];

// Prepacked weights: hi/lo bf16x2 (packed along k), transposed to [N][K/2]
__device__ uint32_t g_WmH[(size_t)DIM * DIM / 2];
__device__ uint32_t g_WmL[(size_t)DIM * DIM / 2];
__device__ uint32_t g_W1H[(size_t)NE * II * HD / 2];
__device__ uint32_t g_W1L[(size_t)NE * II * HD / 2];
__device__ uint32_t g_W2H[(size_t)NE * HD * II / 2];
__device__ uint32_t g_W2L[(size_t)NE * HD * II / 2];
__device__ uint32_t g_WoH[(size_t)DIM * DIM / 2];
__device__ uint32_t g_WoL[(size_t)DIM * DIM / 2];

__device__ __forceinline__ float gelu_exact(float x) {
    return 0.5f * x * (1.0f + erff(x * 0.70710678118654752440f));
}
__device__ __forceinline__ uint32_t pack_bf16x2(float e0, float e1) {
    uint32_t r;
    asm("cvt.rn.bf16x2.f32 %0, %1, %2;" : "=r"(r) : "f"(e1), "f"(e0));
    return r;
}
__device__ __forceinline__ float bf16_rt(float x) {
    return __bfloat162float(__float2bfloat16(x));
}
__device__ __forceinline__ void mma_bf16(float* d, const uint32_t* a, const uint32_t* b) {
    asm volatile(
        "mma.sync.aligned.m16n8k16.row.col.f32.bf16.bf16.f32 "
        "{%0,%1,%2,%3}, {%4,%5,%6,%7}, {%8,%9}, {%0,%1,%2,%3};\n"
        : "+f"(d[0]), "+f"(d[1]), "+f"(d[2]), "+f"(d[3])
        : "r"(a[0]), "r"(a[1]), "r"(a[2]), "r"(a[3]), "r"(b[0]), "r"(b[1]));
}
__device__ __forceinline__ void ldsm_x4(uint32_t& r0, uint32_t& r1,
                                        uint32_t& r2, uint32_t& r3, uint32_t addr) {
    asm volatile("ldmatrix.sync.aligned.m8n8.x4.shared.b16 {%0,%1,%2,%3}, [%4];"
                 : "=r"(r0), "=r"(r1), "=r"(r2), "=r"(r3) : "r"(addr));
}
__device__ __forceinline__ uint32_t smem_u32(const void* p) {
    return (uint32_t)__cvta_generic_to_shared(p);
}

#define CP16(dst, src) \
    asm volatile("cp.async.cg.shared.global [%0], [%1], 16;" :: "r"(dst), "l"(src))

// ---------------------------------------------------------------------------
// Weight prepack: B[K][N] (row-major, per expert) -> hi/lo [N][K/2] uint32
// ---------------------------------------------------------------------------
__global__ void prepack_kernel(const float* __restrict__ B,
                               uint32_t* __restrict__ Hi, uint32_t* __restrict__ Lo,
                               int K, int N)
{
    const int e = blockIdx.z;
    B  += (size_t)e * K * N;
    Hi += (size_t)e * N * (K / 2);
    Lo += (size_t)e * N * (K / 2);

    __shared__ float tile[64][33];
    const int tid = threadIdx.x;
    const int k0 = blockIdx.y * 64;
    const int n0 = blockIdx.x * 32;

#pragma unroll
    for (int i = 0; i < 8; i++) {
        const int row = i * 8 + (tid >> 5);
        const int col = tid & 31;
        tile[row][col] = B[(size_t)(k0 + row) * N + n0 + col];
    }
    __syncthreads();

#pragma unroll
    for (int j = 0; j < 4; j++) {
        const int nl = (tid >> 5) * 4 + j;
        const int kp = tid & 31;
        const float x0 = tile[2 * kp][nl];
        const float x1 = tile[2 * kp + 1][nl];
        const float h0 = bf16_rt(x0), h1 = bf16_rt(x1);
        const size_t o = (size_t)(n0 + nl) * (K / 2) + k0 / 2 + kp;
        Hi[o] = pack_bf16x2(h0, h1);
        Lo[o] = pack_bf16x2(x0 - h0, x1 - h1);
    }
}

// ---------------------------------------------------------------------------
// bf16-split tensor GEMM (R9 + A smem double-buffer + B smem triple-buffer,
// ONE __syncthreads per k-tile).
// Block 128x128, K-tile 32, 256 threads (8 warps, 64x32 warp tile).
// Dynamic smem, 10 tiles of [128][20] uint32:
//   tiles 0/1: AsH/AsL stage 0    tiles 2/3: AsH/AsL stage 1
//   tiles 4+2j / 5+2j: BsH/BsL stage j (j=0..2)
// ---------------------------------------------------------------------------
#define TSTRIDE 20
#define TILE_B  (128 * TSTRIDE * 4)       // 10240 bytes
#define SMEM_BYTES (10 * TILE_B)          // 102400

template<bool GROUPED, bool GATHER, bool DO_GELU>
__global__ __launch_bounds__(256, 2)
void mma_gemm(const float* __restrict__ Asrc,
              const uint32_t* __restrict__ BpH, const uint32_t* __restrict__ BpL,
              const float* __restrict__ biasAll, float* __restrict__ Cout,
              int M, int N, int K)
{
    extern __shared__ __align__(16) uint32_t smem[];

    int rows = M, segBase = 0, m0, n0;
    const float* bias;
    if (GROUPED) {
        const int e = blockIdx.y;
        rows    = g_counts[e];
        m0      = blockIdx.x * 128;
        if (m0 >= rows) return;
        segBase = g_offsets[e];
        n0      = blockIdx.z * 128;
        BpH    += (size_t)e * N * (K / 2);
        BpL    += (size_t)e * N * (K / 2);
        bias    = biasAll + (size_t)e * N;
    } else {
        m0   = blockIdx.y * 128;
        n0   = blockIdx.x * 128;
        bias = biasAll;
    }

    const int tid  = threadIdx.x;
    const int lane = tid & 31;
    const int wid  = tid >> 5;
    const int g    = lane >> 2;
    const int tig  = lane & 3;
    const int wm   = (wid & 1) * 64;
    const int wn   = (wid >> 1) * 32;

    const uint32_t base = smem_u32(smem);

    // A loads: thread covers 4 rows, float4 at col (tid&7)*4
    const int acol = (tid & 7) * 4;
    const float* arow[4];
    bool aval[4];
#pragma unroll
    for (int v = 0; v < 4; v++) {
        const int r  = v * 32 + (tid >> 3);
        const int gr = m0 + r;
        if (GROUPED) {
            aval[v] = (gr < rows);
            int row = 0;
            if (aval[v]) row = GATHER ? g_perm[segBase + gr] : (segBase + gr);
            arow[v] = Asrc + (size_t)row * K + acol;
        } else {
            aval[v] = true;
            arow[v] = Asrc + (size_t)gr * K + acol;
        }
    }
    // A smem store offset within a stage (uint2 at [r][acol>>1])
    const uint32_t a_st = (((tid >> 3) * TSTRIDE) + (acol >> 1)) * 4;

    // B loads: thread covers col = tid>>1, 8 kpairs starting (tid&1)*8
    const int bcol  = tid >> 1;
    const int bkp   = (tid & 1) * 8;
    const uint32_t* bptrH = BpH + (size_t)(n0 + bcol) * (K / 2) + bkp;
    const uint32_t* bptrL = BpL + (size_t)(n0 + bcol) * (K / 2) + bkp;
    const uint32_t b_st = (bcol * TSTRIDE + bkp) * 4;

    // ldmatrix per-lane addresses (stage-local byte offsets)
    const uint32_t a_off = (((wm + (lane & 15)) * TSTRIDE) + ((lane >> 4) * 4)) * 4;
    const uint32_t b_off = (((wn + ((lane >> 4) & 1) * 8 + (lane & 7)) * TSTRIDE)
                            + (((lane >> 3) & 1) * 4)) * 4;

    float acc[4][4][4];
#pragma unroll
    for (int m = 0; m < 4; m++)
#pragma unroll
        for (int n = 0; n < 4; n++)
#pragma unroll
            for (int i = 0; i < 4; i++) acc[m][n][i] = 0.0f;

    const int KT = K / 32;

    // helper: issue B tile kt into stage j (2 tiles H/L)
    auto issue_B = [&](int kt, int j) {
        const int kpo = kt * 16;
        const uint32_t dB = base + (4 + 2 * j) * TILE_B + b_st;
        CP16(dB,               bptrH + kpo);
        CP16(dB + 16,          bptrH + kpo + 4);
        CP16(dB + TILE_B,      bptrL + kpo);
        CP16(dB + TILE_B + 16, bptrL + kpo + 4);
        asm volatile("cp.async.commit_group;");
    };
    // helper: convert areg -> A stage sa
    float4 areg[4];
    auto convert_A = [&](int sa) {
        const uint32_t sbase = base + sa * 2 * TILE_B;
#pragma unroll
        for (int v = 0; v < 4; v++) {
            const float hx = bf16_rt(areg[v].x), hy = bf16_rt(areg[v].y);
            const float hz = bf16_rt(areg[v].z), hw = bf16_rt(areg[v].w);
            uint2 hv, lv;
            hv.x = pack_bf16x2(hx, hy);
            hv.y = pack_bf16x2(hz, hw);
            lv.x = pack_bf16x2(areg[v].x - hx, areg[v].y - hy);
            lv.y = pack_bf16x2(areg[v].z - hz, areg[v].w - hw);
            const uint32_t d = sbase + a_st + v * 32 * TSTRIDE * 4;
            asm volatile("st.shared.v2.b32 [%0], {%1,%2};" :: "r"(d), "r"(hv.x), "r"(hv.y));
            asm volatile("st.shared.v2.b32 [%0], {%1,%2};"
                         :: "r"(d + TILE_B), "r"(lv.x), "r"(lv.y));
        }
    };
    auto fetch_A = [&](int kt) {
        const int ko = kt * 32;
#pragma unroll
        for (int v = 0; v < 4; v++) {
            areg[v] = make_float4(0.f, 0.f, 0.f, 0.f);
            if (aval[v]) areg[v] = *reinterpret_cast<const float4*>(arow[v] + ko);
        }
    };

    // ---- preloop: A0 regs->convert->stage0; B0,B1 cp.async; A1 regs ----
    fetch_A(0);
    convert_A(0);
    issue_B(0, 0);
    if (KT > 1) { fetch_A(1); issue_B(1, 1); }

    for (int kt = 0; kt < KT; kt++) {
        const int sA = kt & 1;
        const int sB = kt % 3;
        if (kt + 1 < KT) asm volatile("cp.async.wait_group 1;" ::: "memory");
        else             asm volatile("cp.async.wait_group 0;" ::: "memory");
        __syncthreads();

        // issue B(kt+2) into stage (kt+2)%3 (last read at iter kt-1, safe now)
        if (kt + 2 < KT) issue_B(kt + 2, (kt + 2) % 3);

        const uint32_t aH_addr = base + sA * 2 * TILE_B + a_off;
        const uint32_t aL_addr = aH_addr + TILE_B;
        const uint32_t bH_addr = base + (4 + 2 * sB) * TILE_B + b_off;
        const uint32_t bL_addr = bH_addr + TILE_B;

#pragma unroll
        for (int ks = 0; ks < 2; ks++) {
            const uint32_t ksb = ks * 32;
            uint32_t bH[4][2], bL[4][2];
            ldsm_x4(bH[0][0], bH[0][1], bH[1][0], bH[1][1], bH_addr + ksb);
            ldsm_x4(bH[2][0], bH[2][1], bH[3][0], bH[3][1], bH_addr + ksb + 16 * TSTRIDE * 4);
            ldsm_x4(bL[0][0], bL[0][1], bL[1][0], bL[1][1], bL_addr + ksb);
            ldsm_x4(bL[2][0], bL[2][1], bL[3][0], bL[3][1], bL_addr + ksb + 16 * TSTRIDE * 4);
#pragma unroll
            for (int m = 0; m < 4; m++) {
                const uint32_t mb = m * 16 * TSTRIDE * 4;
                uint32_t aH[4], aL[4];
                ldsm_x4(aH[0], aH[1], aH[2], aH[3], aH_addr + mb + ksb);
                ldsm_x4(aL[0], aL[1], aL[2], aL[3], aL_addr + mb + ksb);
#pragma unroll
                for (int n = 0; n < 4; n++) {
                    mma_bf16(acc[m][n], aH, bH[n]);
                    mma_bf16(acc[m][n], aH, bL[n]);
                    mma_bf16(acc[m][n], aL, bH[n]);
                }
            }
        }

        if (kt + 1 < KT) {
            // areg holds tile kt+1: convert into A stage (kt+1)&1.
            // That stage was last read at iter kt-1 (barrier-separated). Safe.
            convert_A((kt + 1) & 1);
            if (kt + 2 < KT) fetch_A(kt + 2);
        }
    }

    // ---- epilogue ----
#pragma unroll
    for (int n = 0; n < 4; n++) {
        const int col = n0 + wn + n * 8 + 2 * tig;
        const float b0 = bias[col];
        const float b1 = bias[col + 1];
#pragma unroll
        for (int m = 0; m < 4; m++) {
            const int r0 = wm + m * 16 + g;
            float v00 = acc[m][n][0] + b0;
            float v01 = acc[m][n][1] + b1;
            float v10 = acc[m][n][2] + b0;
            float v11 = acc[m][n][3] + b1;
            if (DO_GELU) {
                v00 = gelu_exact(v00); v01 = gelu_exact(v01);
                v10 = gelu_exact(v10); v11 = gelu_exact(v11);
            }
            if (GROUPED) {
                if (m0 + r0 < rows) {
                    float* p = Cout + (size_t)(segBase + m0 + r0) * N + col;
                    *reinterpret_cast<float2*>(p) = make_float2(v00, v01);
                }
                if (m0 + r0 + 8 < rows) {
                    float* p = Cout + (size_t)(segBase + m0 + r0 + 8) * N + col;
                    *reinterpret_cast<float2*>(p) = make_float2(v10, v11);
                }
            } else {
                float* p0 = Cout + (size_t)(m0 + r0) * N + col;
                float* p1 = Cout + (size_t)(m0 + r0 + 8) * N + col;
                *reinterpret_cast<float2*>(p0) = make_float2(v00, v01);
                *reinterpret_cast<float2*>(p1) = make_float2(v10, v11);
            }
        }
    }
}

// ---------------------------------------------------------------------------
// Routing: one warp per sub-token.
// ---------------------------------------------------------------------------
__global__ void routing_kernel(const float* __restrict__ emb)
{
    const int warp = (blockIdx.x * blockDim.x + threadIdx.x) >> 5;
    const int lane = threadIdx.x & 31;
    if (warp >= NSUB) return;

    const float* trow = g_h + (size_t)warp * HD;
    const float tv0 = trow[lane];
    const float tv1 = trow[lane + 32];
    const float tv2 = trow[lane + 64];
    const float tv3 = trow[lane + 96];

    float logits[NE];
#pragma unroll
    for (int e = 0; e < NE; e++) {
        float p = tv0 * emb[(lane      ) * NE + e]
                + tv1 * emb[(lane + 32 ) * NE + e]
                + tv2 * emb[(lane + 64 ) * NE + e]
                + tv3 * emb[(lane + 96 ) * NE + e];
#pragma unroll
        for (int s = 16; s > 0; s >>= 1) p += __shfl_xor_sync(0xffffffffu, p, s);
        logits[e] = p;
    }

    float mx = logits[0];
#pragma unroll
    for (int e = 1; e < NE; e++) mx = fmaxf(mx, logits[e]);
    float sum = 0.0f;
#pragma unroll
    for (int e = 0; e < NE; e++) { logits[e] = expf(logits[e] - mx); sum += logits[e]; }
    const float inv = 1.0f / sum;

    int i0 = 0; float v0 = logits[0];
#pragma unroll
    for (int e = 1; e < NE; e++) if (logits[e] > v0) { v0 = logits[e]; i0 = e; }
    int i1 = -1; float v1 = -1.0f;
#pragma unroll
    for (int e = 0; e < NE; e++) if (e != i0 && logits[e] > v1) { v1 = logits[e]; i1 = e; }

    if (lane == 0) {
        g_topi[2 * warp + 0] = i0;
        g_topi[2 * warp + 1] = i1;
        g_topw[2 * warp + 0] = v0 * inv;
        g_topw[2 * warp + 1] = v1 * inv;
    }
}

// ---------------------------------------------------------------------------
// Routing bookkeeping (block/warp aggregated atomics)
// ---------------------------------------------------------------------------
__global__ void zero_counts() {
    int i = threadIdx.x;
    if (i < NE) { g_counts[i] = 0; g_cursor[i] = 0; }
}
__global__ void hist_kernel() {
    __shared__ int loc[NE];
    if (threadIdx.x < NE) loc[threadIdx.x] = 0;
    __syncthreads();
    const int i    = blockIdx.x * blockDim.x + threadIdx.x;
    const int lane = threadIdx.x & 31;
    const int e    = g_topi[i];
    unsigned mask  = __match_any_sync(0xffffffffu, e);
    if (lane == (__ffs(mask) - 1)) atomicAdd(&loc[e], __popc(mask));
    __syncthreads();
    if (threadIdx.x < NE && loc[threadIdx.x])
        atomicAdd(&g_counts[threadIdx.x], loc[threadIdx.x]);
}
__global__ void scan_kernel() {
    int s = 0;
    for (int e = 0; e < NE; e++) { g_offsets[e] = s; s += g_counts[e]; }
    g_offsets[NE] = s;
}
__global__ void scatter_kernel() {
    __shared__ int bcnt[NE];
    __shared__ int bbase[NE];
    if (threadIdx.x < NE) bcnt[threadIdx.x] = 0;
    __syncthreads();

    const int i    = blockIdx.x * blockDim.x + threadIdx.x;
    const int lane = threadIdx.x & 31;
    const int e    = g_topi[i];

    unsigned mask    = __match_any_sync(0xffffffffu, e);
    const int leader = __ffs(mask) - 1;
    const int lrank  = __popc(mask & ((1u << lane) - 1));
    int wbase = 0;
    if (lane == leader) wbase = atomicAdd(&bcnt[e], __popc(mask));
    wbase = __shfl_sync(0xffffffffu, wbase, leader);
    __syncthreads();

    if (threadIdx.x < NE)
        bbase[threadIdx.x] = bcnt[threadIdx.x]
            ? atomicAdd(&g_cursor[threadIdx.x], bcnt[threadIdx.x]) : 0;
    __syncthreads();

    const int slot = g_offsets[e] + bbase[e] + wbase + lrank;
    g_perm[slot] = i >> 1;
    g_pos[i] = slot;
}

// ---------------------------------------------------------------------------
// Combine: comb[t, :] = w0 * eo[pos0, :] + w1 * eo[pos1, :]  (float4)
// ---------------------------------------------------------------------------
__global__ void combine_kernel() {
    int idx = blockIdx.x * blockDim.x + threadIdx.x;   // over NSUB*(HD/4)
    int t = idx >> 5;
    int j = idx & 31;
    float w0 = g_topw[2 * t + 0];
    float w1 = g_topw[2 * t + 1];
    int   s0 = g_pos [2 * t + 0];
    int   s1 = g_pos [2 * t + 1];
    float4 a = reinterpret_cast<const float4*>(g_eo)[(size_t)s0 * (HD / 4) + j];
    float4 b = reinterpret_cast<const float4*>(g_eo)[(size_t)s1 * (HD / 4) + j];
    float4 c;
    c.x = w0 * a.x + w1 * b.x;
    c.y = w0 * a.y + w1 * b.y;
    c.z = w0 * a.z + w1 * b.z;
    c.w = w0 * a.w + w1 * b.w;
    reinterpret_cast<float4*>(g_comb)[idx] = c;
}

// ---------------------------------------------------------------------------
// Launch
// ---------------------------------------------------------------------------
extern "C" void kernel_launch(void* const* d_in, const int* in_sizes, int n_in,
                              void* d_out, int out_size)
{
    (void)in_sizes; (void)n_in; (void)out_size;
    const float* x   = (const float*)d_in[0];
    const float* Wm  = (const float*)d_in[1];
    const float* bm  = (const float*)d_in[2];
    const float* emb = (const float*)d_in[3];
    const float* W1  = (const float*)d_in[4];
    const float* b1  = (const float*)d_in[5];
    const float* W2  = (const float*)d_in[6];
    const float* b2  = (const float*)d_in[7];
    const float* Wo  = (const float*)d_in[8];
    const float* bo  = (const float*)d_in[9];
    float* out = (float*)d_out;

    float *h_p, *comb_p, *hmid_p, *eo_p;
    cudaGetSymbolAddress((void**)&h_p,    g_h);
    cudaGetSymbolAddress((void**)&comb_p, g_comb);
    cudaGetSymbolAddress((void**)&hmid_p, g_hmid);
    cudaGetSymbolAddress((void**)&eo_p,   g_eo);
    uint32_t *WmH, *WmL, *W1H, *W1L, *W2H, *W2L, *WoH, *WoL;
    cudaGetSymbolAddress((void**)&WmH, g_WmH); cudaGetSymbolAddress((void**)&WmL, g_WmL);
    cudaGetSymbolAddress((void**)&W1H, g_W1H); cudaGetSymbolAddress((void**)&W1L, g_W1L);
    cudaGetSymbolAddress((void**)&W2H, g_W2H); cudaGetSymbolAddress((void**)&W2L, g_W2L);
    cudaGetSymbolAddress((void**)&WoH, g_WoH); cudaGetSymbolAddress((void**)&WoL, g_WoL);

    cudaFuncSetAttribute(mma_gemm<false,false,false>,
                         cudaFuncAttributeMaxDynamicSharedMemorySize, SMEM_BYTES);
    cudaFuncSetAttribute(mma_gemm<true,true,true>,
                         cudaFuncAttributeMaxDynamicSharedMemorySize, SMEM_BYTES);
    cudaFuncSetAttribute(mma_gemm<true,false,false>,
                         cudaFuncAttributeMaxDynamicSharedMemorySize, SMEM_BYTES);

    // 0) prepack weights (transpose + bf16 hi/lo split)
    prepack_kernel<<<dim3(DIM/32, DIM/64, 1),  256>>>(Wm, WmH, WmL, DIM, DIM);
    prepack_kernel<<<dim3(II/32,  HD/64,  NE), 256>>>(W1, W1H, W1L, HD, II);
    prepack_kernel<<<dim3(HD/32,  II/64,  NE), 256>>>(W2, W2H, W2L, II, HD);
    prepack_kernel<<<dim3(DIM/32, DIM/64, 1),  256>>>(Wo, WoH, WoL, DIM, DIM);

    // 1) h = x @ Wm + bm
    mma_gemm<false,false,false><<<dim3(DIM/128, NTOK/128), 256, SMEM_BYTES>>>(
        x, WmH, WmL, bm, h_p, NTOK, DIM, DIM);

    // 2) routing
    routing_kernel<<<NSUB / 16, 512>>>(emb);

    // 3) expert bookkeeping
    zero_counts<<<1, 32>>>();
    hist_kernel<<<NPAIR / 256, 256>>>();
    scan_kernel<<<1, 1>>>();
    scatter_kernel<<<NPAIR / 256, 256>>>();

    // 4) hmid = gelu(t @ W1[e] + b1[e])   K=128, N=512 (gathered A)
    mma_gemm<true,true,true><<<dim3(NPAIR/128, NE, II/128), 256, SMEM_BYTES>>>(
        h_p, W1H, W1L, b1, hmid_p, 0, II, HD);

    // 5) eo = hmid @ W2[e] + b2[e]        K=512, N=128
    mma_gemm<true,false,false><<<dim3(NPAIR/128, NE, HD/128), 256, SMEM_BYTES>>>(
        hmid_p, W2H, W2L, b2, eo_p, 0, HD, II);

    // 6) combine
    combine_kernel<<<(NSUB * HD / 4) / 256, 256>>>();

    // 7) out = comb @ Wo + bo
    mma_gemm<false,false,false><<<dim3(DIM/128, NTOK/128), 256, SMEM_BYTES>>>(
        comb_p, WoH, WoL, bo, out, NTOK, DIM, DIM);
}

// round 11
// speedup vs baseline: 1.5906x; 1.0671x over previous
#include <cuda_runtime.h>
#include <cuda_bf16.h>
#include <math.h>
#include <stdint.h>

// ---------------------------------------------------------------------------
// Problem constants
// ---------------------------------------------------------------------------
#define BSZ   4
#define LEN   2048
#define DIM   1024
#define NH    8
#define NE    16
#define TOPK  2
#define HD    128
#define II    512
#define NTOK  (BSZ*LEN)    // 8192
#define NSUB  (NTOK*NH)    // 65536
#define NPAIR (NSUB*TOPK)  // 131072
#define MAXTILES (NPAIR/128 + NE)   // 1040

// ---------------------------------------------------------------------------
// Device scratch
// ---------------------------------------------------------------------------
__device__ float g_h   [(size_t)NTOK * DIM];
__device__ float g_comb[(size_t)NTOK * DIM];
__device__ float g_hmid[(size_t)NPAIR * II];
__device__ float g_eo  [(size_t)NPAIR * HD];
__device__ int   g_topi[NPAIR];
__device__ float g_topw[NPAIR];
__device__ int   g_perm[NPAIR];
__device__ int   g_pos [NPAIR];
__device__ int   g_counts[NE];
__device__ int   g_cursor[NE];
__device__ int   g_offsets[NE + 1];
__device__ int2  g_tilemap[MAXTILES];
__device__ int   g_ntiles;

// Prepacked weights: hi/lo bf16x2 (packed along k), transposed to [N][K/2]
__device__ uint32_t g_WmH[(size_t)DIM * DIM / 2];
__device__ uint32_t g_WmL[(size_t)DIM * DIM / 2];
__device__ uint32_t g_W1H[(size_t)NE * II * HD / 2];
__device__ uint32_t g_W1L[(size_t)NE * II * HD / 2];
__device__ uint32_t g_W2H[(size_t)NE * HD * II / 2];
__device__ uint32_t g_W2L[(size_t)NE * HD * II / 2];
__device__ uint32_t g_WoH[(size_t)DIM * DIM / 2];
__device__ uint32_t g_WoL[(size_t)DIM * DIM / 2];

__device__ __forceinline__ float gelu_exact(float x) {
    return 0.5f * x * (1.0f + erff(x * 0.70710678118654752440f));
}
__device__ __forceinline__ uint32_t pack_bf16x2(float e0, float e1) {
    uint32_t r;
    asm("cvt.rn.bf16x2.f32 %0, %1, %2;" : "=r"(r) : "f"(e1), "f"(e0));
    return r;
}
__device__ __forceinline__ float bf16_rt(float x) {
    return __bfloat162float(__float2bfloat16(x));
}
__device__ __forceinline__ void mma_bf16(float* d, const uint32_t* a, const uint32_t* b) {
    asm volatile(
        "mma.sync.aligned.m16n8k16.row.col.f32.bf16.bf16.f32 "
        "{%0,%1,%2,%3}, {%4,%5,%6,%7}, {%8,%9}, {%0,%1,%2,%3};\n"
        : "+f"(d[0]), "+f"(d[1]), "+f"(d[2]), "+f"(d[3])
        : "r"(a[0]), "r"(a[1]), "r"(a[2]), "r"(a[3]), "r"(b[0]), "r"(b[1]));
}
__device__ __forceinline__ void ldsm_x4(uint32_t& r0, uint32_t& r1,
                                        uint32_t& r2, uint32_t& r3, uint32_t addr) {
    asm volatile("ldmatrix.sync.aligned.m8n8.x4.shared.b16 {%0,%1,%2,%3}, [%4];"
                 : "=r"(r0), "=r"(r1), "=r"(r2), "=r"(r3) : "r"(addr));
}
__device__ __forceinline__ uint32_t smem_u32(const void* p) {
    return (uint32_t)__cvta_generic_to_shared(p);
}

#define CP16(dst, src) \
    asm volatile("cp.async.cg.shared.global [%0], [%1], 16;" :: "r"(dst), "l"(src))

// ---------------------------------------------------------------------------
// Weight prepack: B[K][N] (row-major, per expert) -> hi/lo [N][K/2] uint32
// ---------------------------------------------------------------------------
__global__ void prepack_kernel(const float* __restrict__ B,
                               uint32_t* __restrict__ Hi, uint32_t* __restrict__ Lo,
                               int K, int N)
{
    const int e = blockIdx.z;
    B  += (size_t)e * K * N;
    Hi += (size_t)e * N * (K / 2);
    Lo += (size_t)e * N * (K / 2);

    __shared__ float tile[64][33];
    const int tid = threadIdx.x;
    const int k0 = blockIdx.y * 64;
    const int n0 = blockIdx.x * 32;

#pragma unroll
    for (int i = 0; i < 8; i++) {
        const int row = i * 8 + (tid >> 5);
        const int col = tid & 31;
        tile[row][col] = B[(size_t)(k0 + row) * N + n0 + col];
    }
    __syncthreads();

#pragma unroll
    for (int j = 0; j < 4; j++) {
        const int nl = (tid >> 5) * 4 + j;
        const int kp = tid & 31;
        const float x0 = tile[2 * kp][nl];
        const float x1 = tile[2 * kp + 1][nl];
        const float h0 = bf16_rt(x0), h1 = bf16_rt(x1);
        const size_t o = (size_t)(n0 + nl) * (K / 2) + k0 / 2 + kp;
        Hi[o] = pack_bf16x2(h0, h1);
        Lo[o] = pack_bf16x2(x0 - h0, x1 - h1);
    }
}

// ---------------------------------------------------------------------------
// bf16-split tensor GEMM (R10 pipeline; GROUPED path uses flat tile worklist).
// Block 128x128, K-tile 32, 256 threads (8 warps, 64x32 warp tile).
// Dynamic smem, 10 tiles of [128][20] uint32:
//   tiles 0/1: AsH/AsL stage 0    tiles 2/3: AsH/AsL stage 1
//   tiles 4+2j / 5+2j: BsH/BsL stage j (j=0..2)
// Grouped grid: (MAXTILES, N/128). Dense grid: (N/128, M/128).
// ---------------------------------------------------------------------------
#define TSTRIDE 20
#define TILE_B  (128 * TSTRIDE * 4)       // 10240 bytes
#define SMEM_BYTES (10 * TILE_B)          // 102400

template<bool GROUPED, bool GATHER, bool DO_GELU>
__global__ __launch_bounds__(256, 2)
void mma_gemm(const float* __restrict__ Asrc,
              const uint32_t* __restrict__ BpH, const uint32_t* __restrict__ BpL,
              const float* __restrict__ biasAll, float* __restrict__ Cout,
              int M, int N, int K)
{
    extern __shared__ __align__(16) uint32_t smem[];

    int rows = M, segBase = 0, m0, n0;
    const float* bias;
    if (GROUPED) {
        if ((int)blockIdx.x >= g_ntiles) return;
        const int2 tm = g_tilemap[blockIdx.x];
        const int e = tm.x;
        m0      = tm.y;
        rows    = g_counts[e];
        segBase = g_offsets[e];
        n0      = blockIdx.y * 128;
        BpH    += (size_t)e * N * (K / 2);
        BpL    += (size_t)e * N * (K / 2);
        bias    = biasAll + (size_t)e * N;
    } else {
        m0   = blockIdx.y * 128;
        n0   = blockIdx.x * 128;
        bias = biasAll;
    }

    const int tid  = threadIdx.x;
    const int lane = tid & 31;
    const int wid  = tid >> 5;
    const int g    = lane >> 2;
    const int tig  = lane & 3;
    const int wm   = (wid & 1) * 64;
    const int wn   = (wid >> 1) * 32;

    const uint32_t base = smem_u32(smem);

    // A loads: thread covers 4 rows, float4 at col (tid&7)*4
    const int acol = (tid & 7) * 4;
    const float* arow[4];
    bool aval[4];
#pragma unroll
    for (int v = 0; v < 4; v++) {
        const int r  = v * 32 + (tid >> 3);
        const int gr = m0 + r;
        if (GROUPED) {
            aval[v] = (gr < rows);
            int row = 0;
            if (aval[v]) row = GATHER ? g_perm[segBase + gr] : (segBase + gr);
            arow[v] = Asrc + (size_t)row * K + acol;
        } else {
            aval[v] = true;
            arow[v] = Asrc + (size_t)gr * K + acol;
        }
    }
    // A smem store offset within a stage (uint2 at [r][acol>>1])
    const uint32_t a_st = (((tid >> 3) * TSTRIDE) + (acol >> 1)) * 4;

    // B loads: thread covers col = tid>>1, 8 kpairs starting (tid&1)*8
    const int bcol  = tid >> 1;
    const int bkp   = (tid & 1) * 8;
    const uint32_t* bptrH = BpH + (size_t)(n0 + bcol) * (K / 2) + bkp;
    const uint32_t* bptrL = BpL + (size_t)(n0 + bcol) * (K / 2) + bkp;
    const uint32_t b_st = (bcol * TSTRIDE + bkp) * 4;

    // ldmatrix per-lane addresses (stage-local byte offsets)
    const uint32_t a_off = (((wm + (lane & 15)) * TSTRIDE) + ((lane >> 4) * 4)) * 4;
    const uint32_t b_off = (((wn + ((lane >> 4) & 1) * 8 + (lane & 7)) * TSTRIDE)
                            + (((lane >> 3) & 1) * 4)) * 4;

    float acc[4][4][4];
#pragma unroll
    for (int m = 0; m < 4; m++)
#pragma unroll
        for (int n = 0; n < 4; n++)
#pragma unroll
            for (int i = 0; i < 4; i++) acc[m][n][i] = 0.0f;

    const int KT = K / 32;

    // helper: issue B tile kt into stage j (2 tiles H/L)
    auto issue_B = [&](int kt, int j) {
        const int kpo = kt * 16;
        const uint32_t dB = base + (4 + 2 * j) * TILE_B + b_st;
        CP16(dB,               bptrH + kpo);
        CP16(dB + 16,          bptrH + kpo + 4);
        CP16(dB + TILE_B,      bptrL + kpo);
        CP16(dB + TILE_B + 16, bptrL + kpo + 4);
        asm volatile("cp.async.commit_group;");
    };
    // helper: convert areg -> A stage sa
    float4 areg[4];
    auto convert_A = [&](int sa) {
        const uint32_t sbase = base + sa * 2 * TILE_B;
#pragma unroll
        for (int v = 0; v < 4; v++) {
            const float hx = bf16_rt(areg[v].x), hy = bf16_rt(areg[v].y);
            const float hz = bf16_rt(areg[v].z), hw = bf16_rt(areg[v].w);
            uint2 hv, lv;
            hv.x = pack_bf16x2(hx, hy);
            hv.y = pack_bf16x2(hz, hw);
            lv.x = pack_bf16x2(areg[v].x - hx, areg[v].y - hy);
            lv.y = pack_bf16x2(areg[v].z - hz, areg[v].w - hw);
            const uint32_t d = sbase + a_st + v * 32 * TSTRIDE * 4;
            asm volatile("st.shared.v2.b32 [%0], {%1,%2};" :: "r"(d), "r"(hv.x), "r"(hv.y));
            asm volatile("st.shared.v2.b32 [%0], {%1,%2};"
                         :: "r"(d + TILE_B), "r"(lv.x), "r"(lv.y));
        }
    };
    auto fetch_A = [&](int kt) {
        const int ko = kt * 32;
#pragma unroll
        for (int v = 0; v < 4; v++) {
            areg[v] = make_float4(0.f, 0.f, 0.f, 0.f);
            if (aval[v]) areg[v] = *reinterpret_cast<const float4*>(arow[v] + ko);
        }
    };

    // ---- preloop: A0 regs->convert->stage0; B0,B1 cp.async; A1 regs ----
    fetch_A(0);
    convert_A(0);
    issue_B(0, 0);
    if (KT > 1) { fetch_A(1); issue_B(1, 1); }

    for (int kt = 0; kt < KT; kt++) {
        const int sA = kt & 1;
        const int sB = kt % 3;
        if (kt + 1 < KT) asm volatile("cp.async.wait_group 1;" ::: "memory");
        else             asm volatile("cp.async.wait_group 0;" ::: "memory");
        __syncthreads();

        // issue B(kt+2) into stage (kt+2)%3 (last read at iter kt-1, safe now)
        if (kt + 2 < KT) issue_B(kt + 2, (kt + 2) % 3);

        const uint32_t aH_addr = base + sA * 2 * TILE_B + a_off;
        const uint32_t aL_addr = aH_addr + TILE_B;
        const uint32_t bH_addr = base + (4 + 2 * sB) * TILE_B + b_off;
        const uint32_t bL_addr = bH_addr + TILE_B;

#pragma unroll
        for (int ks = 0; ks < 2; ks++) {
            const uint32_t ksb = ks * 32;
            uint32_t bH[4][2], bL[4][2];
            ldsm_x4(bH[0][0], bH[0][1], bH[1][0], bH[1][1], bH_addr + ksb);
            ldsm_x4(bH[2][0], bH[2][1], bH[3][0], bH[3][1], bH_addr + ksb + 16 * TSTRIDE * 4);
            ldsm_x4(bL[0][0], bL[0][1], bL[1][0], bL[1][1], bL_addr + ksb);
            ldsm_x4(bL[2][0], bL[2][1], bL[3][0], bL[3][1], bL_addr + ksb + 16 * TSTRIDE * 4);
#pragma unroll
            for (int m = 0; m < 4; m++) {
                const uint32_t mb = m * 16 * TSTRIDE * 4;
                uint32_t aH[4], aL[4];
                ldsm_x4(aH[0], aH[1], aH[2], aH[3], aH_addr + mb + ksb);
                ldsm_x4(aL[0], aL[1], aL[2], aL[3], aL_addr + mb + ksb);
#pragma unroll
                for (int n = 0; n < 4; n++) {
                    mma_bf16(acc[m][n], aH, bH[n]);
                    mma_bf16(acc[m][n], aH, bL[n]);
                    mma_bf16(acc[m][n], aL, bH[n]);
                }
            }
        }

        if (kt + 1 < KT) {
            convert_A((kt + 1) & 1);
            if (kt + 2 < KT) fetch_A(kt + 2);
        }
    }

    // ---- epilogue ----
#pragma unroll
    for (int n = 0; n < 4; n++) {
        const int col = n0 + wn + n * 8 + 2 * tig;
        const float b0 = bias[col];
        const float b1 = bias[col + 1];
#pragma unroll
        for (int m = 0; m < 4; m++) {
            const int r0 = wm + m * 16 + g;
            float v00 = acc[m][n][0] + b0;
            float v01 = acc[m][n][1] + b1;
            float v10 = acc[m][n][2] + b0;
            float v11 = acc[m][n][3] + b1;
            if (DO_GELU) {
                v00 = gelu_exact(v00); v01 = gelu_exact(v01);
                v10 = gelu_exact(v10); v11 = gelu_exact(v11);
            }
            if (GROUPED) {
                if (m0 + r0 < rows) {
                    float* p = Cout + (size_t)(segBase + m0 + r0) * N + col;
                    *reinterpret_cast<float2*>(p) = make_float2(v00, v01);
                }
                if (m0 + r0 + 8 < rows) {
                    float* p = Cout + (size_t)(segBase + m0 + r0 + 8) * N + col;
                    *reinterpret_cast<float2*>(p) = make_float2(v10, v11);
                }
            } else {
                float* p0 = Cout + (size_t)(m0 + r0) * N + col;
                float* p1 = Cout + (size_t)(m0 + r0 + 8) * N + col;
                *reinterpret_cast<float2*>(p0) = make_float2(v00, v01);
                *reinterpret_cast<float2*>(p1) = make_float2(v10, v11);
            }
        }
    }
}

// ---------------------------------------------------------------------------
// Routing: one warp per sub-token.
// ---------------------------------------------------------------------------
__global__ void routing_kernel(const float* __restrict__ emb)
{
    const int warp = (blockIdx.x * blockDim.x + threadIdx.x) >> 5;
    const int lane = threadIdx.x & 31;
    if (warp >= NSUB) return;

    const float* trow = g_h + (size_t)warp * HD;
    const float tv0 = trow[lane];
    const float tv1 = trow[lane + 32];
    const float tv2 = trow[lane + 64];
    const float tv3 = trow[lane + 96];

    float logits[NE];
#pragma unroll
    for (int e = 0; e < NE; e++) {
        float p = tv0 * emb[(lane      ) * NE + e]
                + tv1 * emb[(lane + 32 ) * NE + e]
                + tv2 * emb[(lane + 64 ) * NE + e]
                + tv3 * emb[(lane + 96 ) * NE + e];
#pragma unroll
        for (int s = 16; s > 0; s >>= 1) p += __shfl_xor_sync(0xffffffffu, p, s);
        logits[e] = p;
    }

    float mx = logits[0];
#pragma unroll
    for (int e = 1; e < NE; e++) mx = fmaxf(mx, logits[e]);
    float sum = 0.0f;
#pragma unroll
    for (int e = 0; e < NE; e++) { logits[e] = expf(logits[e] - mx); sum += logits[e]; }
    const float inv = 1.0f / sum;

    int i0 = 0; float v0 = logits[0];
#pragma unroll
    for (int e = 1; e < NE; e++) if (logits[e] > v0) { v0 = logits[e]; i0 = e; }
    int i1 = -1; float v1 = -1.0f;
#pragma unroll
    for (int e = 0; e < NE; e++) if (e != i0 && logits[e] > v1) { v1 = logits[e]; i1 = e; }

    if (lane == 0) {
        g_topi[2 * warp + 0] = i0;
        g_topi[2 * warp + 1] = i1;
        g_topw[2 * warp + 0] = v0 * inv;
        g_topw[2 * warp + 1] = v1 * inv;
    }
}

// ---------------------------------------------------------------------------
// Routing bookkeeping (block/warp aggregated atomics)
// ---------------------------------------------------------------------------
__global__ void zero_counts() {
    int i = threadIdx.x;
    if (i < NE) { g_counts[i] = 0; g_cursor[i] = 0; }
}
__global__ void hist_kernel() {
    __shared__ int loc[NE];
    if (threadIdx.x < NE) loc[threadIdx.x] = 0;
    __syncthreads();
    const int i    = blockIdx.x * blockDim.x + threadIdx.x;
    const int lane = threadIdx.x & 31;
    const int e    = g_topi[i];
    unsigned mask  = __match_any_sync(0xffffffffu, e);
    if (lane == (__ffs(mask) - 1)) atomicAdd(&loc[e], __popc(mask));
    __syncthreads();
    if (threadIdx.x < NE && loc[threadIdx.x])
        atomicAdd(&g_counts[threadIdx.x], loc[threadIdx.x]);
}
__global__ void scan_kernel() {
    int s = 0;
    for (int e = 0; e < NE; e++) { g_offsets[e] = s; s += g_counts[e]; }
    g_offsets[NE] = s;
}
// Build flat (expert, m0) worklist for grouped GEMM tiles.
__global__ void build_tiles() {
    const int e = threadIdx.x;
    if (e >= NE) return;
    // tile-start for this expert = sum of ceil(counts/128) for experts before
    int start = 0;
#pragma unroll
    for (int j = 0; j < NE; j++) {
        int tj = (g_counts[j] + 127) >> 7;
        if (j < e) start += tj;
        if (e == NE - 1 && j == NE - 1) g_ntiles = start + tj;
    }
    const int nt = (g_counts[e] + 127) >> 7;
    for (int t = 0; t < nt; t++)
        g_tilemap[start + t] = make_int2(e, t << 7);
}
__global__ void scatter_kernel() {
    __shared__ int bcnt[NE];
    __shared__ int bbase[NE];
    if (threadIdx.x < NE) bcnt[threadIdx.x] = 0;
    __syncthreads();

    const int i    = blockIdx.x * blockDim.x + threadIdx.x;
    const int lane = threadIdx.x & 31;
    const int e    = g_topi[i];

    unsigned mask    = __match_any_sync(0xffffffffu, e);
    const int leader = __ffs(mask) - 1;
    const int lrank  = __popc(mask & ((1u << lane) - 1));
    int wbase = 0;
    if (lane == leader) wbase = atomicAdd(&bcnt[e], __popc(mask));
    wbase = __shfl_sync(0xffffffffu, wbase, leader);
    __syncthreads();

    if (threadIdx.x < NE)
        bbase[threadIdx.x] = bcnt[threadIdx.x]
            ? atomicAdd(&g_cursor[threadIdx.x], bcnt[threadIdx.x]) : 0;
    __syncthreads();

    const int slot = g_offsets[e] + bbase[e] + wbase + lrank;
    g_perm[slot] = i >> 1;
    g_pos[i] = slot;
}

// ---------------------------------------------------------------------------
// Combine: comb[t, :] = w0 * eo[pos0, :] + w1 * eo[pos1, :]  (float4)
// ---------------------------------------------------------------------------
__global__ void combine_kernel() {
    int idx = blockIdx.x * blockDim.x + threadIdx.x;   // over NSUB*(HD/4)
    int t = idx >> 5;
    int j = idx & 31;
    float w0 = g_topw[2 * t + 0];
    float w1 = g_topw[2 * t + 1];
    int   s0 = g_pos [2 * t + 0];
    int   s1 = g_pos [2 * t + 1];
    float4 a = reinterpret_cast<const float4*>(g_eo)[(size_t)s0 * (HD / 4) + j];
    float4 b = reinterpret_cast<const float4*>(g_eo)[(size_t)s1 * (HD / 4) + j];
    float4 c;
    c.x = w0 * a.x + w1 * b.x;
    c.y = w0 * a.y + w1 * b.y;
    c.z = w0 * a.z + w1 * b.z;
    c.w = w0 * a.w + w1 * b.w;
    reinterpret_cast<float4*>(g_comb)[idx] = c;
}

// ---------------------------------------------------------------------------
// Launch
// ---------------------------------------------------------------------------
extern "C" void kernel_launch(void* const* d_in, const int* in_sizes, int n_in,
                              void* d_out, int out_size)
{
    (void)in_sizes; (void)n_in; (void)out_size;
    const float* x   = (const float*)d_in[0];
    const float* Wm  = (const float*)d_in[1];
    const float* bm  = (const float*)d_in[2];
    const float* emb = (const float*)d_in[3];
    const float* W1  = (const float*)d_in[4];
    const float* b1  = (const float*)d_in[5];
    const float* W2  = (const float*)d_in[6];
    const float* b2  = (const float*)d_in[7];
    const float* Wo  = (const float*)d_in[8];
    const float* bo  = (const float*)d_in[9];
    float* out = (float*)d_out;

    float *h_p, *comb_p, *hmid_p, *eo_p;
    cudaGetSymbolAddress((void**)&h_p,    g_h);
    cudaGetSymbolAddress((void**)&comb_p, g_comb);
    cudaGetSymbolAddress((void**)&hmid_p, g_hmid);
    cudaGetSymbolAddress((void**)&eo_p,   g_eo);
    uint32_t *WmH, *WmL, *W1H, *W1L, *W2H, *W2L, *WoH, *WoL;
    cudaGetSymbolAddress((void**)&WmH, g_WmH); cudaGetSymbolAddress((void**)&WmL, g_WmL);
    cudaGetSymbolAddress((void**)&W1H, g_W1H); cudaGetSymbolAddress((void**)&W1L, g_W1L);
    cudaGetSymbolAddress((void**)&W2H, g_W2H); cudaGetSymbolAddress((void**)&W2L, g_W2L);
    cudaGetSymbolAddress((void**)&WoH, g_WoH); cudaGetSymbolAddress((void**)&WoL, g_WoL);

    cudaFuncSetAttribute(mma_gemm<false,false,false>,
                         cudaFuncAttributeMaxDynamicSharedMemorySize, SMEM_BYTES);
    cudaFuncSetAttribute(mma_gemm<true,true,true>,
                         cudaFuncAttributeMaxDynamicSharedMemorySize, SMEM_BYTES);
    cudaFuncSetAttribute(mma_gemm<true,false,false>,
                         cudaFuncAttributeMaxDynamicSharedMemorySize, SMEM_BYTES);

    // 0) prepack weights (transpose + bf16 hi/lo split)
    prepack_kernel<<<dim3(DIM/32, DIM/64, 1),  256>>>(Wm, WmH, WmL, DIM, DIM);
    prepack_kernel<<<dim3(II/32,  HD/64,  NE), 256>>>(W1, W1H, W1L, HD, II);
    prepack_kernel<<<dim3(HD/32,  II/64,  NE), 256>>>(W2, W2H, W2L, II, HD);
    prepack_kernel<<<dim3(DIM/32, DIM/64, 1),  256>>>(Wo, WoH, WoL, DIM, DIM);

    // 1) h = x @ Wm + bm
    mma_gemm<false,false,false><<<dim3(DIM/128, NTOK/128), 256, SMEM_BYTES>>>(
        x, WmH, WmL, bm, h_p, NTOK, DIM, DIM);

    // 2) routing
    routing_kernel<<<NSUB / 16, 512>>>(emb);

    // 3) expert bookkeeping + tile worklist
    zero_counts<<<1, 32>>>();
    hist_kernel<<<NPAIR / 256, 256>>>();
    scan_kernel<<<1, 1>>>();
    build_tiles<<<1, NE>>>();
    scatter_kernel<<<NPAIR / 256, 256>>>();

    // 4) hmid = gelu(t @ W1[e] + b1[e])   K=128, N=512 (gathered A)
    mma_gemm<true,true,true><<<dim3(MAXTILES, II/128), 256, SMEM_BYTES>>>(
        h_p, W1H, W1L, b1, hmid_p, 0, II, HD);

    // 5) eo = hmid @ W2[e] + b2[e]        K=512, N=128
    mma_gemm<true,false,false><<<dim3(MAXTILES, HD/128), 256, SMEM_BYTES>>>(
        hmid_p, W2H, W2L, b2, eo_p, 0, HD, II);

    // 6) combine
    combine_kernel<<<(NSUB * HD / 4) / 256, 256>>>();

    // 7) out = comb @ Wo + bo
    mma_gemm<false,false,false><<<dim3(DIM/128, NTOK/128), 256, SMEM_BYTES>>>(
        comb_p, WoH, WoL, bo, out, NTOK, DIM, DIM);
}

// round 12
// speedup vs baseline: 1.5941x; 1.0022x over previous
#include <cuda_runtime.h>
#include <cuda_bf16.h>
#include <math.h>
#include <stdint.h>

// ---------------------------------------------------------------------------
// Problem constants
// ---------------------------------------------------------------------------
#define BSZ   4
#define LEN   2048
#define DIM   1024
#define NH    8
#define NE    16
#define TOPK  2
#define HD    128
#define II    512
#define NTOK  (BSZ*LEN)    // 8192
#define NSUB  (NTOK*NH)    // 65536
#define NPAIR (NSUB*TOPK)  // 131072
#define MAXTILES (NPAIR/128 + NE)   // 1040

// ---------------------------------------------------------------------------
// Device scratch
// ---------------------------------------------------------------------------
__device__ float g_h   [(size_t)NTOK * DIM];
__device__ float g_comb[(size_t)NTOK * DIM];
__device__ float g_hmid[(size_t)NPAIR * II];
__device__ int   g_topi[NPAIR];
__device__ float g_topw[NPAIR];
__device__ int   g_perm[NPAIR];
__device__ float g_wslot[NPAIR];
__device__ int   g_counts[NE];
__device__ int   g_cursor[NE];
__device__ int   g_offsets[NE + 1];
__device__ int2  g_tilemap[MAXTILES];
__device__ int   g_ntiles;

// Prepacked weights: hi/lo bf16x2 (packed along k), transposed to [N][K/2]
__device__ uint32_t g_WmH[(size_t)DIM * DIM / 2];
__device__ uint32_t g_WmL[(size_t)DIM * DIM / 2];
__device__ uint32_t g_W1H[(size_t)NE * II * HD / 2];
__device__ uint32_t g_W1L[(size_t)NE * II * HD / 2];
__device__ uint32_t g_W2H[(size_t)NE * HD * II / 2];
__device__ uint32_t g_W2L[(size_t)NE * HD * II / 2];
__device__ uint32_t g_WoH[(size_t)DIM * DIM / 2];
__device__ uint32_t g_WoL[(size_t)DIM * DIM / 2];

__device__ __forceinline__ float gelu_exact(float x) {
    return 0.5f * x * (1.0f + erff(x * 0.70710678118654752440f));
}
__device__ __forceinline__ uint32_t pack_bf16x2(float e0, float e1) {
    uint32_t r;
    asm("cvt.rn.bf16x2.f32 %0, %1, %2;" : "=r"(r) : "f"(e1), "f"(e0));
    return r;
}
__device__ __forceinline__ float bf16_rt(float x) {
    return __bfloat162float(__float2bfloat16(x));
}
__device__ __forceinline__ void mma_bf16(float* d, const uint32_t* a, const uint32_t* b) {
    asm volatile(
        "mma.sync.aligned.m16n8k16.row.col.f32.bf16.bf16.f32 "
        "{%0,%1,%2,%3}, {%4,%5,%6,%7}, {%8,%9}, {%0,%1,%2,%3};\n"
        : "+f"(d[0]), "+f"(d[1]), "+f"(d[2]), "+f"(d[3])
        : "r"(a[0]), "r"(a[1]), "r"(a[2]), "r"(a[3]), "r"(b[0]), "r"(b[1]));
}
__device__ __forceinline__ void ldsm_x4(uint32_t& r0, uint32_t& r1,
                                        uint32_t& r2, uint32_t& r3, uint32_t addr) {
    asm volatile("ldmatrix.sync.aligned.m8n8.x4.shared.b16 {%0,%1,%2,%3}, [%4];"
                 : "=r"(r0), "=r"(r1), "=r"(r2), "=r"(r3) : "r"(addr));
}
__device__ __forceinline__ uint32_t smem_u32(const void* p) {
    return (uint32_t)__cvta_generic_to_shared(p);
}

#define CP16(dst, src) \
    asm volatile("cp.async.cg.shared.global [%0], [%1], 16;" :: "r"(dst), "l"(src))

// ---------------------------------------------------------------------------
// Weight prepack: B[K][N] (row-major, per expert) -> hi/lo [N][K/2] uint32
// ---------------------------------------------------------------------------
__global__ void prepack_kernel(const float* __restrict__ B,
                               uint32_t* __restrict__ Hi, uint32_t* __restrict__ Lo,
                               int K, int N)
{
    const int e = blockIdx.z;
    B  += (size_t)e * K * N;
    Hi += (size_t)e * N * (K / 2);
    Lo += (size_t)e * N * (K / 2);

    __shared__ float tile[64][33];
    const int tid = threadIdx.x;
    const int k0 = blockIdx.y * 64;
    const int n0 = blockIdx.x * 32;

#pragma unroll
    for (int i = 0; i < 8; i++) {
        const int row = i * 8 + (tid >> 5);
        const int col = tid & 31;
        tile[row][col] = B[(size_t)(k0 + row) * N + n0 + col];
    }
    __syncthreads();

#pragma unroll
    for (int j = 0; j < 4; j++) {
        const int nl = (tid >> 5) * 4 + j;
        const int kp = tid & 31;
        const float x0 = tile[2 * kp][nl];
        const float x1 = tile[2 * kp + 1][nl];
        const float h0 = bf16_rt(x0), h1 = bf16_rt(x1);
        const size_t o = (size_t)(n0 + nl) * (K / 2) + k0 / 2 + kp;
        Hi[o] = pack_bf16x2(h0, h1);
        Lo[o] = pack_bf16x2(x0 - h0, x1 - h1);
    }
}

// ---------------------------------------------------------------------------
// Zero the combine accumulator (float4 stream).
// ---------------------------------------------------------------------------
__global__ void zero_comb() {
    int i = blockIdx.x * blockDim.x + threadIdx.x;
    reinterpret_cast<float4*>(g_comb)[i] = make_float4(0.f, 0.f, 0.f, 0.f);
}

// ---------------------------------------------------------------------------
// bf16-split tensor GEMM (R11 pipeline; flat tile worklist for GROUPED).
// OUT_ATOMIC: epilogue scales by g_wslot[slot] and atomically accumulates
// into g_comb[g_perm[slot]*N + col] (fused MoE combine).
// ---------------------------------------------------------------------------
#define TSTRIDE 20
#define TILE_B  (128 * TSTRIDE * 4)       // 10240 bytes
#define SMEM_BYTES (10 * TILE_B)          // 102400

template<bool GROUPED, bool GATHER, bool DO_GELU, bool OUT_ATOMIC>
__global__ __launch_bounds__(256, 2)
void mma_gemm(const float* __restrict__ Asrc,
              const uint32_t* __restrict__ BpH, const uint32_t* __restrict__ BpL,
              const float* __restrict__ biasAll, float* __restrict__ Cout,
              int M, int N, int K)
{
    extern __shared__ __align__(16) uint32_t smem[];

    int rows = M, segBase = 0, m0, n0;
    const float* bias;
    if (GROUPED) {
        if ((int)blockIdx.x >= g_ntiles) return;
        const int2 tm = g_tilemap[blockIdx.x];
        const int e = tm.x;
        m0      = tm.y;
        rows    = g_counts[e];
        segBase = g_offsets[e];
        n0      = blockIdx.y * 128;
        BpH    += (size_t)e * N * (K / 2);
        BpL    += (size_t)e * N * (K / 2);
        bias    = biasAll + (size_t)e * N;
    } else {
        m0   = blockIdx.y * 128;
        n0   = blockIdx.x * 128;
        bias = biasAll;
    }

    const int tid  = threadIdx.x;
    const int lane = tid & 31;
    const int wid  = tid >> 5;
    const int g    = lane >> 2;
    const int tig  = lane & 3;
    const int wm   = (wid & 1) * 64;
    const int wn   = (wid >> 1) * 32;

    const uint32_t base = smem_u32(smem);

    // A loads: thread covers 4 rows, float4 at col (tid&7)*4
    const int acol = (tid & 7) * 4;
    const float* arow[4];
    bool aval[4];
#pragma unroll
    for (int v = 0; v < 4; v++) {
        const int r  = v * 32 + (tid >> 3);
        const int gr = m0 + r;
        if (GROUPED) {
            aval[v] = (gr < rows);
            int row = 0;
            if (aval[v]) row = GATHER ? g_perm[segBase + gr] : (segBase + gr);
            arow[v] = Asrc + (size_t)row * K + acol;
        } else {
            aval[v] = true;
            arow[v] = Asrc + (size_t)gr * K + acol;
        }
    }
    // A smem store offset within a stage (uint2 at [r][acol>>1])
    const uint32_t a_st = (((tid >> 3) * TSTRIDE) + (acol >> 1)) * 4;

    // B loads: thread covers col = tid>>1, 8 kpairs starting (tid&1)*8
    const int bcol  = tid >> 1;
    const int bkp   = (tid & 1) * 8;
    const uint32_t* bptrH = BpH + (size_t)(n0 + bcol) * (K / 2) + bkp;
    const uint32_t* bptrL = BpL + (size_t)(n0 + bcol) * (K / 2) + bkp;
    const uint32_t b_st = (bcol * TSTRIDE + bkp) * 4;

    // ldmatrix per-lane addresses (stage-local byte offsets)
    const uint32_t a_off = (((wm + (lane & 15)) * TSTRIDE) + ((lane >> 4) * 4)) * 4;
    const uint32_t b_off = (((wn + ((lane >> 4) & 1) * 8 + (lane & 7)) * TSTRIDE)
                            + (((lane >> 3) & 1) * 4)) * 4;

    float acc[4][4][4];
#pragma unroll
    for (int m = 0; m < 4; m++)
#pragma unroll
        for (int n = 0; n < 4; n++)
#pragma unroll
            for (int i = 0; i < 4; i++) acc[m][n][i] = 0.0f;

    const int KT = K / 32;

    auto issue_B = [&](int kt, int j) {
        const int kpo = kt * 16;
        const uint32_t dB = base + (4 + 2 * j) * TILE_B + b_st;
        CP16(dB,               bptrH + kpo);
        CP16(dB + 16,          bptrH + kpo + 4);
        CP16(dB + TILE_B,      bptrL + kpo);
        CP16(dB + TILE_B + 16, bptrL + kpo + 4);
        asm volatile("cp.async.commit_group;");
    };
    float4 areg[4];
    auto convert_A = [&](int sa) {
        const uint32_t sbase = base + sa * 2 * TILE_B;
#pragma unroll
        for (int v = 0; v < 4; v++) {
            const float hx = bf16_rt(areg[v].x), hy = bf16_rt(areg[v].y);
            const float hz = bf16_rt(areg[v].z), hw = bf16_rt(areg[v].w);
            uint2 hv, lv;
            hv.x = pack_bf16x2(hx, hy);
            hv.y = pack_bf16x2(hz, hw);
            lv.x = pack_bf16x2(areg[v].x - hx, areg[v].y - hy);
            lv.y = pack_bf16x2(areg[v].z - hz, areg[v].w - hw);
            const uint32_t d = sbase + a_st + v * 32 * TSTRIDE * 4;
            asm volatile("st.shared.v2.b32 [%0], {%1,%2};" :: "r"(d), "r"(hv.x), "r"(hv.y));
            asm volatile("st.shared.v2.b32 [%0], {%1,%2};"
                         :: "r"(d + TILE_B), "r"(lv.x), "r"(lv.y));
        }
    };
    auto fetch_A = [&](int kt) {
        const int ko = kt * 32;
#pragma unroll
        for (int v = 0; v < 4; v++) {
            areg[v] = make_float4(0.f, 0.f, 0.f, 0.f);
            if (aval[v]) areg[v] = *reinterpret_cast<const float4*>(arow[v] + ko);
        }
    };

    // ---- preloop ----
    fetch_A(0);
    convert_A(0);
    issue_B(0, 0);
    if (KT > 1) { fetch_A(1); issue_B(1, 1); }

    for (int kt = 0; kt < KT; kt++) {
        const int sA = kt & 1;
        const int sB = kt % 3;
        if (kt + 1 < KT) asm volatile("cp.async.wait_group 1;" ::: "memory");
        else             asm volatile("cp.async.wait_group 0;" ::: "memory");
        __syncthreads();

        if (kt + 2 < KT) issue_B(kt + 2, (kt + 2) % 3);

        const uint32_t aH_addr = base + sA * 2 * TILE_B + a_off;
        const uint32_t aL_addr = aH_addr + TILE_B;
        const uint32_t bH_addr = base + (4 + 2 * sB) * TILE_B + b_off;
        const uint32_t bL_addr = bH_addr + TILE_B;

#pragma unroll
        for (int ks = 0; ks < 2; ks++) {
            const uint32_t ksb = ks * 32;
            uint32_t bH[4][2], bL[4][2];
            ldsm_x4(bH[0][0], bH[0][1], bH[1][0], bH[1][1], bH_addr + ksb);
            ldsm_x4(bH[2][0], bH[2][1], bH[3][0], bH[3][1], bH_addr + ksb + 16 * TSTRIDE * 4);
            ldsm_x4(bL[0][0], bL[0][1], bL[1][0], bL[1][1], bL_addr + ksb);
            ldsm_x4(bL[2][0], bL[2][1], bL[3][0], bL[3][1], bL_addr + ksb + 16 * TSTRIDE * 4);
#pragma unroll
            for (int m = 0; m < 4; m++) {
                const uint32_t mb = m * 16 * TSTRIDE * 4;
                uint32_t aH[4], aL[4];
                ldsm_x4(aH[0], aH[1], aH[2], aH[3], aH_addr + mb + ksb);
                ldsm_x4(aL[0], aL[1], aL[2], aL[3], aL_addr + mb + ksb);
#pragma unroll
                for (int n = 0; n < 4; n++) {
                    mma_bf16(acc[m][n], aH, bH[n]);
                    mma_bf16(acc[m][n], aH, bL[n]);
                    mma_bf16(acc[m][n], aL, bH[n]);
                }
            }
        }

        if (kt + 1 < KT) {
            convert_A((kt + 1) & 1);
            if (kt + 2 < KT) fetch_A(kt + 2);
        }
    }

    // ---- epilogue ----
    if (OUT_ATOMIC) {
        // fused combine: Cout treated as [NSUB][N] accumulator
#pragma unroll
        for (int m = 0; m < 4; m++) {
            const int r0 = wm + m * 16 + g;
            int   tok[2]; float w[2]; bool ok[2];
#pragma unroll
            for (int h = 0; h < 2; h++) {
                const int gr = m0 + r0 + 8 * h;
                ok[h] = gr < rows;
                if (ok[h]) {
                    const int slot = segBase + gr;
                    tok[h] = g_perm[slot];
                    w[h]   = g_wslot[slot];
                } else { tok[h] = 0; w[h] = 0.f; }
            }
#pragma unroll
            for (int n = 0; n < 4; n++) {
                const int col = n0 + wn + n * 8 + 2 * tig;
                const float b0 = bias[col];
                const float b1 = bias[col + 1];
                if (ok[0]) {
                    float* p = Cout + (size_t)tok[0] * N + col;
                    atomicAdd(p,     w[0] * (acc[m][n][0] + b0));
                    atomicAdd(p + 1, w[0] * (acc[m][n][1] + b1));
                }
                if (ok[1]) {
                    float* p = Cout + (size_t)tok[1] * N + col;
                    atomicAdd(p,     w[1] * (acc[m][n][2] + b0));
                    atomicAdd(p + 1, w[1] * (acc[m][n][3] + b1));
                }
            }
        }
    } else {
#pragma unroll
        for (int n = 0; n < 4; n++) {
            const int col = n0 + wn + n * 8 + 2 * tig;
            const float b0 = bias[col];
            const float b1 = bias[col + 1];
#pragma unroll
            for (int m = 0; m < 4; m++) {
                const int r0 = wm + m * 16 + g;
                float v00 = acc[m][n][0] + b0;
                float v01 = acc[m][n][1] + b1;
                float v10 = acc[m][n][2] + b0;
                float v11 = acc[m][n][3] + b1;
                if (DO_GELU) {
                    v00 = gelu_exact(v00); v01 = gelu_exact(v01);
                    v10 = gelu_exact(v10); v11 = gelu_exact(v11);
                }
                if (GROUPED) {
                    if (m0 + r0 < rows) {
                        float* p = Cout + (size_t)(segBase + m0 + r0) * N + col;
                        *reinterpret_cast<float2*>(p) = make_float2(v00, v01);
                    }
                    if (m0 + r0 + 8 < rows) {
                        float* p = Cout + (size_t)(segBase + m0 + r0 + 8) * N + col;
                        *reinterpret_cast<float2*>(p) = make_float2(v10, v11);
                    }
                } else {
                    float* p0 = Cout + (size_t)(m0 + r0) * N + col;
                    float* p1 = Cout + (size_t)(m0 + r0 + 8) * N + col;
                    *reinterpret_cast<float2*>(p0) = make_float2(v00, v01);
                    *reinterpret_cast<float2*>(p1) = make_float2(v10, v11);
                }
            }
        }
    }
}

// ---------------------------------------------------------------------------
// Routing: one warp per sub-token + fused expert histogram (block-aggregated).
// ---------------------------------------------------------------------------
__global__ void routing_kernel(const float* __restrict__ emb)
{
    __shared__ int loc[NE];
    if (threadIdx.x < NE) loc[threadIdx.x] = 0;
    __syncthreads();

    const int warp = (blockIdx.x * blockDim.x + threadIdx.x) >> 5;
    const int lane = threadIdx.x & 31;

    const float* trow = g_h + (size_t)warp * HD;
    const float tv0 = trow[lane];
    const float tv1 = trow[lane + 32];
    const float tv2 = trow[lane + 64];
    const float tv3 = trow[lane + 96];

    float logits[NE];
#pragma unroll
    for (int e = 0; e < NE; e++) {
        float p = tv0 * emb[(lane      ) * NE + e]
                + tv1 * emb[(lane + 32 ) * NE + e]
                + tv2 * emb[(lane + 64 ) * NE + e]
                + tv3 * emb[(lane + 96 ) * NE + e];
#pragma unroll
        for (int s = 16; s > 0; s >>= 1) p += __shfl_xor_sync(0xffffffffu, p, s);
        logits[e] = p;
    }

    float mx = logits[0];
#pragma unroll
    for (int e = 1; e < NE; e++) mx = fmaxf(mx, logits[e]);
    float sum = 0.0f;
#pragma unroll
    for (int e = 0; e < NE; e++) { logits[e] = expf(logits[e] - mx); sum += logits[e]; }
    const float inv = 1.0f / sum;

    int i0 = 0; float v0 = logits[0];
#pragma unroll
    for (int e = 1; e < NE; e++) if (logits[e] > v0) { v0 = logits[e]; i0 = e; }
    int i1 = -1; float v1 = -1.0f;
#pragma unroll
    for (int e = 0; e < NE; e++) if (e != i0 && logits[e] > v1) { v1 = logits[e]; i1 = e; }

    if (lane == 0) {
        g_topi[2 * warp + 0] = i0;
        g_topi[2 * warp + 1] = i1;
        g_topw[2 * warp + 0] = v0 * inv;
        g_topw[2 * warp + 1] = v1 * inv;
        atomicAdd(&loc[i0], 1);
        atomicAdd(&loc[i1], 1);
    }
    __syncthreads();
    if (threadIdx.x < NE && loc[threadIdx.x])
        atomicAdd(&g_counts[threadIdx.x], loc[threadIdx.x]);
}

// ---------------------------------------------------------------------------
// Routing bookkeeping
// ---------------------------------------------------------------------------
__global__ void zero_counts() {
    int i = threadIdx.x;
    if (i < NE) { g_counts[i] = 0; g_cursor[i] = 0; }
}
__global__ void scan_kernel() {
    int s = 0;
    for (int e = 0; e < NE; e++) { g_offsets[e] = s; s += g_counts[e]; }
    g_offsets[NE] = s;
}
// Build flat (expert, m0) worklist for grouped GEMM tiles.
__global__ void build_tiles() {
    const int e = threadIdx.x;
    if (e >= NE) return;
    int start = 0;
#pragma unroll
    for (int j = 0; j < NE; j++) {
        int tj = (g_counts[j] + 127) >> 7;
        if (j < e) start += tj;
        if (e == NE - 1 && j == NE - 1) g_ntiles = start + tj;
    }
    const int nt = (g_counts[e] + 127) >> 7;
    for (int t = 0; t < nt; t++)
        g_tilemap[start + t] = make_int2(e, t << 7);
}
__global__ void scatter_kernel() {
    __shared__ int bcnt[NE];
    __shared__ int bbase[NE];
    if (threadIdx.x < NE) bcnt[threadIdx.x] = 0;
    __syncthreads();

    const int i    = blockIdx.x * blockDim.x + threadIdx.x;
    const int lane = threadIdx.x & 31;
    const int e    = g_topi[i];

    unsigned mask    = __match_any_sync(0xffffffffu, e);
    const int leader = __ffs(mask) - 1;
    const int lrank  = __popc(mask & ((1u << lane) - 1));
    int wbase = 0;
    if (lane == leader) wbase = atomicAdd(&bcnt[e], __popc(mask));
    wbase = __shfl_sync(0xffffffffu, wbase, leader);
    __syncthreads();

    if (threadIdx.x < NE)
        bbase[threadIdx.x] = bcnt[threadIdx.x]
            ? atomicAdd(&g_cursor[threadIdx.x], bcnt[threadIdx.x]) : 0;
    __syncthreads();

    const int slot = g_offsets[e] + bbase[e] + wbase + lrank;
    g_perm[slot]  = i >> 1;
    g_wslot[slot] = g_topw[i];
}

// ---------------------------------------------------------------------------
// Launch
// ---------------------------------------------------------------------------
extern "C" void kernel_launch(void* const* d_in, const int* in_sizes, int n_in,
                              void* d_out, int out_size)
{
    (void)in_sizes; (void)n_in; (void)out_size;
    const float* x   = (const float*)d_in[0];
    const float* Wm  = (const float*)d_in[1];
    const float* bm  = (const float*)d_in[2];
    const float* emb = (const float*)d_in[3];
    const float* W1  = (const float*)d_in[4];
    const float* b1  = (const float*)d_in[5];
    const float* W2  = (const float*)d_in[6];
    const float* b2  = (const float*)d_in[7];
    const float* Wo  = (const float*)d_in[8];
    const float* bo  = (const float*)d_in[9];
    float* out = (float*)d_out;

    float *h_p, *comb_p, *hmid_p;
    cudaGetSymbolAddress((void**)&h_p,    g_h);
    cudaGetSymbolAddress((void**)&comb_p, g_comb);
    cudaGetSymbolAddress((void**)&hmid_p, g_hmid);
    uint32_t *WmH, *WmL, *W1H, *W1L, *W2H, *W2L, *WoH, *WoL;
    cudaGetSymbolAddress((void**)&WmH, g_WmH); cudaGetSymbolAddress((void**)&WmL, g_WmL);
    cudaGetSymbolAddress((void**)&W1H, g_W1H); cudaGetSymbolAddress((void**)&W1L, g_W1L);
    cudaGetSymbolAddress((void**)&W2H, g_W2H); cudaGetSymbolAddress((void**)&W2L, g_W2L);
    cudaGetSymbolAddress((void**)&WoH, g_WoH); cudaGetSymbolAddress((void**)&WoL, g_WoL);

    cudaFuncSetAttribute(mma_gemm<false,false,false,false>,
                         cudaFuncAttributeMaxDynamicSharedMemorySize, SMEM_BYTES);
    cudaFuncSetAttribute(mma_gemm<true,true,true,false>,
                         cudaFuncAttributeMaxDynamicSharedMemorySize, SMEM_BYTES);
    cudaFuncSetAttribute(mma_gemm<true,false,false,true>,
                         cudaFuncAttributeMaxDynamicSharedMemorySize, SMEM_BYTES);

    // 0) prepack weights + zero combine accumulator + zero counts
    zero_comb<<<(NTOK * DIM / 4) / 256, 256>>>();
    zero_counts<<<1, 32>>>();
    prepack_kernel<<<dim3(DIM/32, DIM/64, 1),  256>>>(Wm, WmH, WmL, DIM, DIM);
    prepack_kernel<<<dim3(II/32,  HD/64,  NE), 256>>>(W1, W1H, W1L, HD, II);
    prepack_kernel<<<dim3(HD/32,  II/64,  NE), 256>>>(W2, W2H, W2L, II, HD);
    prepack_kernel<<<dim3(DIM/32, DIM/64, 1),  256>>>(Wo, WoH, WoL, DIM, DIM);

    // 1) h = x @ Wm + bm
    mma_gemm<false,false,false,false><<<dim3(DIM/128, NTOK/128), 256, SMEM_BYTES>>>(
        x, WmH, WmL, bm, h_p, NTOK, DIM, DIM);

    // 2) routing (+ fused histogram)
    routing_kernel<<<NSUB / 16, 512>>>(emb);

    // 3) expert bookkeeping + tile worklist
    scan_kernel<<<1, 1>>>();
    build_tiles<<<1, NE>>>();
    scatter_kernel<<<NPAIR / 256, 256>>>();

    // 4) hmid = gelu(t @ W1[e] + b1[e])   K=128, N=512 (gathered A)
    mma_gemm<true,true,true,false><<<dim3(MAXTILES, II/128), 256, SMEM_BYTES>>>(
        h_p, W1H, W1L, b1, hmid_p, 0, II, HD);

    // 5) eo = hmid @ W2[e] + b2[e], fused w-scaled atomic combine into comb
    mma_gemm<true,false,false,true><<<dim3(MAXTILES, HD/128), 256, SMEM_BYTES>>>(
        hmid_p, W2H, W2L, b2, comb_p, 0, HD, II);

    // 6) out = comb @ Wo + bo
    mma_gemm<false,false,false,false><<<dim3(DIM/128, NTOK/128), 256, SMEM_BYTES>>>(
        comb_p, WoH, WoL, bo, out, NTOK, DIM, DIM);
}